// round 3
// baseline (speedup 1.0000x reference)
#include <cuda_runtime.h>
#include <cuda_bf16.h>

// Problem constants
// B=2, S=2048, D=1024, H=8, HKV=2, HD=128, G=4
#define SCALE_ATT 0.08838834764831845f

// ---------------- device scratch (no allocations allowed) ----------------
__device__ float g_WqEff[1024 * 1024];   // folded q_weight (q_mat absorbed)
__device__ float g_WkEff[256 * 1024];    // folded k_weight (k_mat absorbed)
__device__ float g_bqEff[1024];
__device__ float g_bkEff[256];
__device__ float g_Q[2 * 8 * 2048 * 128];   // (B,H,S,HD)
__device__ float g_K[2 * 2 * 2048 * 128];   // (B,HKV,S,HD)
__device__ float g_V[2 * 2 * 2048 * 128];   // (B,HKV,S,HD)
__device__ float g_O[2 * 2048 * 8 * 128];   // (B,S,H,HD) -> rows for final GEMM

// ---------------- weight folding: Weff[h*128+j, d] = sum_i mat[i,j] * W[h*128+i, d]
template <int WHICH>
__global__ void fold_w_k(const float* __restrict__ W, const float* __restrict__ mat) {
    int o = blockIdx.x;            // output row (h*128 + j)
    int h = o >> 7, j = o & 127;
    int d = blockIdx.y * 256 + threadIdx.x;
    const float* wrow = W + (h * 128) * 1024 + d;
    float acc = 0.f;
#pragma unroll 8
    for (int i = 0; i < 128; i++) acc += mat[i * 128 + j] * wrow[i * 1024];
    if (WHICH == 0) g_WqEff[o * 1024 + d] = acc;
    else            g_WkEff[o * 1024 + d] = acc;
}

template <int WHICH>
__global__ void fold_b_k(const float* __restrict__ bias, const float* __restrict__ mat) {
    const int HOUT = (WHICH == 0) ? 1024 : 256;
    int o = blockIdx.x * blockDim.x + threadIdx.x;
    if (o >= HOUT) return;
    int h = o >> 7, j = o & 127;
    float acc = 0.f;
    for (int i = 0; i < 128; i++) acc += bias[h * 128 + i] * mat[i * 128 + j];
    if (WHICH == 0) g_bqEff[o] = acc;
    else            g_bkEff[o] = acc;
}

// ---------------- SGEMM: C[M,N] = A[M,1024] @ W[N,1024]^T (+bias, scatter epilogue)
// BM=128, BN=64, BK=16, 256 threads, 8x4 microtile.
// MODE 0: A = hidden_states, N=1536 (Q|K|V regions), scatter into g_Q/g_K/g_V (+bias)
// MODE 1: A = g_O, W = o_weight, N=1024, plain store to out
template <int MODE>
__global__ void __launch_bounds__(256) sgemm_k(const float* __restrict__ A_,
                                               const float* __restrict__ Wext,
                                               const float* __restrict__ bv,
                                               float* __restrict__ out) {
    __shared__ float As[16][132];  // [k][m], padded
    __shared__ float Bs[16][68];   // [k][n], padded

    const float* Ap = (MODE == 0) ? A_ : (const float*)g_O;
    int n0 = blockIdx.x * 64;
    int m0 = blockIdx.y * 128;

    const float* Bmat;
    int nb;
    if (MODE == 0) {
        if (n0 < 1024)      { Bmat = g_WqEff; nb = n0; }
        else if (n0 < 1280) { Bmat = g_WkEff; nb = n0 - 1024; }
        else                { Bmat = Wext;    nb = n0 - 1280; }   // v_weight
    } else {
        Bmat = Wext; nb = n0;
    }

    int tid = threadIdx.x;
    int tr = tid >> 4;   // 0..15 -> 8 rows each
    int tc = tid & 15;   // 0..15 -> 4 cols each

    float acc[8][4];
#pragma unroll
    for (int i = 0; i < 8; i++)
#pragma unroll
        for (int j = 0; j < 4; j++) acc[i][j] = 0.f;

    for (int k0 = 0; k0 < 1024; k0 += 16) {
#pragma unroll
        for (int l = 0; l < 8; l++) {
            int flat = l * 256 + tid;
            int mm = flat >> 4, kk = flat & 15;
            As[kk][mm] = Ap[(m0 + mm) * 1024 + k0 + kk];
        }
#pragma unroll
        for (int l = 0; l < 4; l++) {
            int flat = l * 256 + tid;
            int mm = flat >> 4, kk = flat & 15;
            Bs[kk][mm] = Bmat[(nb + mm) * 1024 + k0 + kk];
        }
        __syncthreads();
#pragma unroll
        for (int kk = 0; kk < 16; kk++) {
            float4 t0 = *(const float4*)&As[kk][tr * 8];
            float4 t1 = *(const float4*)&As[kk][tr * 8 + 4];
            float4 t2 = *(const float4*)&Bs[kk][tc * 4];
            float a[8] = {t0.x, t0.y, t0.z, t0.w, t1.x, t1.y, t1.z, t1.w};
            float b[4] = {t2.x, t2.y, t2.z, t2.w};
#pragma unroll
            for (int i = 0; i < 8; i++)
#pragma unroll
                for (int j = 0; j < 4; j++) acc[i][j] += a[i] * b[j];
        }
        __syncthreads();
    }

    if (MODE == 0) {
#pragma unroll
        for (int i = 0; i < 8; i++) {
            int m = m0 + tr * 8 + i;
            int bb = m >> 11, s = m & 2047;
#pragma unroll
            for (int j = 0; j < 4; j++) {
                int n = n0 + tc * 4 + j;
                float v = acc[i][j];
                if (n < 1024) {
                    int h = n >> 7, hd = n & 127;
                    g_Q[(((bb * 8 + h) * 2048) + s) * 128 + hd] = v + g_bqEff[n];
                } else if (n < 1280) {
                    int nn = n - 1024;
                    int h = nn >> 7, hd = nn & 127;
                    g_K[(((bb * 2 + h) * 2048) + s) * 128 + hd] = v + g_bkEff[nn];
                } else {
                    int nn = n - 1280;
                    int h = nn >> 7, hd = nn & 127;
                    g_V[(((bb * 2 + h) * 2048) + s) * 128 + hd] = v + bv[nn];
                }
            }
        }
    } else {
#pragma unroll
        for (int i = 0; i < 8; i++) {
            int m = m0 + tr * 8 + i;
            float4 st = make_float4(acc[i][0], acc[i][1], acc[i][2], acc[i][3]);
            *(float4*)&out[m * 1024 + n0 + tc * 4] = st;
        }
    }
}

// ---------------- RoPE (in-place), cos/sin broadcast over heads
template <int WHICH>
__global__ void rope_k(const float* __restrict__ cosb, const float* __restrict__ sinb) {
    const int NH = (WHICH == 0) ? 8 : 2;
    float* buf = (WHICH == 0) ? g_Q : g_K;
    int idx = blockIdx.x * 256 + threadIdx.x;
    int total = 2 * NH * 2048 * 64;
    if (idx >= total) return;
    int j = idx & 63;
    int t = idx >> 6;
    int s = t & 2047; t >>= 11;
    int h = t % NH;
    int b = t / NH;
    float* p = buf + (((b * NH + h) * 2048) + s) * 128;
    const float* cp = cosb + (b * 2048 + s) * 128;
    const float* sp = sinb + (b * 2048 + s) * 128;
    float x1 = p[j], x2 = p[j + 64];
    p[j]      = x1 * cp[j]      - x2 * sp[j];
    p[j + 64] = x2 * cp[j + 64] + x1 * sp[j + 64];
}

// ---------------- causal flash attention, fp32 SIMT
// Q tile 64 rows, KV tile 32 keys, 128 threads: thread (tr=tid/8, tc=tid%8)
// S-frag 4x4 (rows tr*4.., cols tc*4..); O-frag 4 rows x 16 cols (cols tc*4+32g)
__global__ void __launch_bounds__(128) attn_k() {
    extern __shared__ float sm[];
    float* QsT = sm;                    // [128][68]  (d-major, padded)
    float* KsT = sm + 128 * 68;         // [128][36]
    float* Vs  = KsT + 128 * 36;        // [32][128]  (natural)
    float* Ps  = Vs + 32 * 128;         // [64][36]

    int q0 = blockIdx.x * 64;
    int h = blockIdx.y, b = blockIdx.z;
    int kv = h >> 2;  // G = 4
    const float* Qg = g_Q + (((b * 8 + h) * 2048) + q0) * 128;
    const float* Kg = g_K + ((b * 2 + kv) * 2048) * 128;
    const float* Vg = g_V + ((b * 2 + kv) * 2048) * 128;

    int tid = threadIdx.x;
    int tr = tid >> 3, tc = tid & 7;

    // load Q transposed: QsT[d][r]
    for (int r = 0; r < 64; r++) QsT[tid * 68 + r] = Qg[r * 128 + tid];
    __syncthreads();

    float Of[4][16];
#pragma unroll
    for (int i = 0; i < 4; i++)
#pragma unroll
        for (int c = 0; c < 16; c++) Of[i][c] = 0.f;
    float mrow[4] = {-3e38f, -3e38f, -3e38f, -3e38f};
    float lrow[4] = {0.f, 0.f, 0.f, 0.f};

    int nkt = (q0 >> 5) + 2;  // key tiles up to causal limit
    for (int kt = 0; kt < nkt; kt++) {
        int kbase = kt * 32;
        // load K transposed + V natural
        for (int c = 0; c < 32; c++) KsT[tid * 36 + c] = Kg[(kbase + c) * 128 + tid];
#pragma unroll
        for (int l = 0; l < 8; l++) {
            int idx4 = l * 128 + tid;
            ((float4*)Vs)[idx4] = ((const float4*)(Vg + kbase * 128))[idx4];
        }
        __syncthreads();

        // S = Q K^T (4x4 frag)
        float sf[4][4];
#pragma unroll
        for (int i = 0; i < 4; i++)
#pragma unroll
            for (int j = 0; j < 4; j++) sf[i][j] = 0.f;
#pragma unroll 8
        for (int d = 0; d < 128; d++) {
            float4 tq = *(const float4*)&QsT[d * 68 + tr * 4];
            float4 tk = *(const float4*)&KsT[d * 36 + tc * 4];
            float qa[4] = {tq.x, tq.y, tq.z, tq.w};
            float kb[4] = {tk.x, tk.y, tk.z, tk.w};
#pragma unroll
            for (int i = 0; i < 4; i++)
#pragma unroll
                for (int j = 0; j < 4; j++) sf[i][j] += qa[i] * kb[j];
        }

        // online softmax
#pragma unroll
        for (int i = 0; i < 4; i++) {
            int qg = q0 + tr * 4 + i;
            float mx = -3e38f;
#pragma unroll
            for (int j = 0; j < 4; j++) {
                int kc = kbase + tc * 4 + j;
                float v = (kc <= qg) ? sf[i][j] * SCALE_ATT : -1e30f;
                sf[i][j] = v;
                mx = fmaxf(mx, v);
            }
            mx = fmaxf(mx, __shfl_xor_sync(0xffffffffu, mx, 1));
            mx = fmaxf(mx, __shfl_xor_sync(0xffffffffu, mx, 2));
            mx = fmaxf(mx, __shfl_xor_sync(0xffffffffu, mx, 4));
            float newm = fmaxf(mrow[i], mx);
            float corr = __expf(mrow[i] - newm);
            mrow[i] = newm;
            float ls = 0.f;
#pragma unroll
            for (int j = 0; j < 4; j++) {
                float p = __expf(sf[i][j] - newm);
                sf[i][j] = p;
                ls += p;
            }
            ls += __shfl_xor_sync(0xffffffffu, ls, 1);
            ls += __shfl_xor_sync(0xffffffffu, ls, 2);
            ls += __shfl_xor_sync(0xffffffffu, ls, 4);
            lrow[i] = lrow[i] * corr + ls;
#pragma unroll
            for (int c = 0; c < 16; c++) Of[i][c] *= corr;
            *(float4*)&Ps[(tr * 4 + i) * 36 + tc * 4] =
                make_float4(sf[i][0], sf[i][1], sf[i][2], sf[i][3]);
        }
        __syncthreads();

        // O += P @ V
#pragma unroll 4
        for (int k = 0; k < 32; k++) {
            float pr[4];
#pragma unroll
            for (int i = 0; i < 4; i++) pr[i] = Ps[(tr * 4 + i) * 36 + k];
#pragma unroll
            for (int g = 0; g < 4; g++) {
                float4 vv = *(const float4*)&Vs[k * 128 + tc * 4 + g * 32];
                float vx[4] = {vv.x, vv.y, vv.z, vv.w};
#pragma unroll
                for (int i = 0; i < 4; i++)
#pragma unroll
                    for (int u = 0; u < 4; u++) Of[i][g * 4 + u] += pr[i] * vx[u];
            }
        }
        __syncthreads();
    }

    // epilogue: normalize and store to (B,S,H,HD)
#pragma unroll
    for (int i = 0; i < 4; i++) {
        float inv = 1.f / lrow[i];
        int qrow = q0 + tr * 4 + i;
        float* op = g_O + (((b * 2048 + qrow) * 8) + h) * 128;
#pragma unroll
        for (int g = 0; g < 4; g++) {
            float4 st = make_float4(Of[i][g * 4 + 0] * inv, Of[i][g * 4 + 1] * inv,
                                    Of[i][g * 4 + 2] * inv, Of[i][g * 4 + 3] * inv);
            *(float4*)&op[tc * 4 + g * 32] = st;
        }
    }
}

// ---------------- launch ----------------
extern "C" void kernel_launch(void* const* d_in, const int* in_sizes, int n_in,
                              void* d_out, int out_size) {
    const float* hs   = (const float*)d_in[0];
    const float* cosb = (const float*)d_in[1];
    const float* sinb = (const float*)d_in[2];
    // d_in[3] attention_mask: exactly causal -> implemented analytically
    const float* qw   = (const float*)d_in[4];
    const float* kw   = (const float*)d_in[5];
    const float* vw   = (const float*)d_in[6];
    const float* ow   = (const float*)d_in[7];
    const float* qb   = (const float*)d_in[8];
    const float* kb   = (const float*)d_in[9];
    const float* vb   = (const float*)d_in[10];
    const float* qmat = (const float*)d_in[11];
    const float* kmat = (const float*)d_in[12];
    // d_in[13], d_in[14]: tau_kv / tau_group — permutation + inverse cancel exactly
    float* out = (float*)d_out;

    const int ATTN_SMEM = (128 * 68 + 128 * 36 + 32 * 128 + 64 * 36) * 4;  // 78848 B
    cudaFuncSetAttribute(attn_k, cudaFuncAttributeMaxDynamicSharedMemorySize, ATTN_SMEM);

    // 1) fold q_mat / k_mat into projection weights + biases
    fold_w_k<0><<<dim3(1024, 4), 256>>>(qw, qmat);
    fold_w_k<1><<<dim3(256, 4), 256>>>(kw, kmat);
    fold_b_k<0><<<4, 256>>>(qb, qmat);
    fold_b_k<1><<<1, 256>>>(kb, kmat);

    // 2) fused QKV projection (M=4096, N=1536) with scatter epilogue
    sgemm_k<0><<<dim3(24, 32), 256>>>(hs, vw, vb, nullptr);

    // 3) RoPE in-place on Q and K
    rope_k<0><<<8192, 256>>>(cosb, sinb);
    rope_k<1><<<2048, 256>>>(cosb, sinb);

    // 4) causal flash attention (GQA, G=4)
    attn_k<<<dim3(32, 8, 2), 128, ATTN_SMEM>>>();

    // 5) output projection (M=4096, N=1024)
    sgemm_k<1><<<dim3(16, 32), 256>>>(nullptr, ow, nullptr, out);
}

// round 4
// speedup vs baseline: 1.0060x; 1.0060x over previous
#include <cuda_runtime.h>
#include <cuda_bf16.h>

// Problem constants
// B=2, S=2048, D=1024, H=8, HKV=2, HD=128, G=4
#define SCALE_ATT 0.08838834764831845f

// ---------------- device scratch (no allocations allowed) ----------------
__device__ float g_WqEff[1024 * 1024];   // folded q_weight (q_mat absorbed)
__device__ float g_WkEff[256 * 1024];    // folded k_weight (k_mat absorbed)
__device__ float g_bqEff[1024];
__device__ float g_bkEff[256];
__device__ float g_Q[2 * 8 * 2048 * 128];   // (B,H,S,HD)
__device__ float g_K[2 * 2 * 2048 * 128];   // (B,HKV,S,HD)
__device__ float g_V[2 * 2 * 2048 * 128];   // (B,HKV,S,HD)
__device__ float g_O[2 * 2048 * 8 * 128];   // (B,S,H,HD) -> rows for final GEMM

// ---------------- weight folding: Weff[h*128+j, d] = sum_i mat[i,j] * W[h*128+i, d]
template <int WHICH>
__global__ void fold_w_k(const float* __restrict__ W, const float* __restrict__ mat) {
    int o = blockIdx.x;            // output row (h*128 + j)
    int h = o >> 7, j = o & 127;
    int d = blockIdx.y * 256 + threadIdx.x;
    const float* wrow = W + (h * 128) * 1024 + d;
    float acc = 0.f;
#pragma unroll 8
    for (int i = 0; i < 128; i++) acc += mat[i * 128 + j] * wrow[i * 1024];
    if (WHICH == 0) g_WqEff[o * 1024 + d] = acc;
    else            g_WkEff[o * 1024 + d] = acc;
}

template <int WHICH>
__global__ void fold_b_k(const float* __restrict__ bias, const float* __restrict__ mat) {
    const int HOUT = (WHICH == 0) ? 1024 : 256;
    int o = blockIdx.x * blockDim.x + threadIdx.x;
    if (o >= HOUT) return;
    int h = o >> 7, j = o & 127;
    float acc = 0.f;
    for (int i = 0; i < 128; i++) acc += bias[h * 128 + i] * mat[i * 128 + j];
    if (WHICH == 0) g_bqEff[o] = acc;
    else            g_bkEff[o] = acc;
}

// ---------------- SGEMM: C[M,N] = A[M,1024] @ W[N,1024]^T (+bias, scatter epilogue)
// BM=128, BN=64, BK=16, 256 threads, 8x4 microtile.
// MODE 0: A = hidden_states, N=1536 (Q|K|V regions), scatter into g_Q/g_K/g_V (+bias)
// MODE 1: A = g_O, W = o_weight, N=1024, plain store to out
template <int MODE>
__global__ void __launch_bounds__(256) sgemm_k(const float* __restrict__ A_,
                                               const float* __restrict__ Wext,
                                               const float* __restrict__ bv,
                                               float* __restrict__ out) {
    __shared__ float As[16][132];  // [k][m], padded
    __shared__ float Bs[16][68];   // [k][n], padded

    const float* Ap = (MODE == 0) ? A_ : (const float*)g_O;
    int n0 = blockIdx.x * 64;
    int m0 = blockIdx.y * 128;

    const float* Bmat;
    int nb;
    if (MODE == 0) {
        if (n0 < 1024)      { Bmat = g_WqEff; nb = n0; }
        else if (n0 < 1280) { Bmat = g_WkEff; nb = n0 - 1024; }
        else                { Bmat = Wext;    nb = n0 - 1280; }   // v_weight
    } else {
        Bmat = Wext; nb = n0;
    }

    int tid = threadIdx.x;
    int tr = tid >> 4;   // 0..15 -> 8 rows each
    int tc = tid & 15;   // 0..15 -> 4 cols each

    float acc[8][4];
#pragma unroll
    for (int i = 0; i < 8; i++)
#pragma unroll
        for (int j = 0; j < 4; j++) acc[i][j] = 0.f;

    for (int k0 = 0; k0 < 1024; k0 += 16) {
#pragma unroll
        for (int l = 0; l < 8; l++) {
            int flat = l * 256 + tid;
            int mm = flat >> 4, kk = flat & 15;
            As[kk][mm] = Ap[(m0 + mm) * 1024 + k0 + kk];
        }
#pragma unroll
        for (int l = 0; l < 4; l++) {
            int flat = l * 256 + tid;
            int mm = flat >> 4, kk = flat & 15;
            Bs[kk][mm] = Bmat[(nb + mm) * 1024 + k0 + kk];
        }
        __syncthreads();
#pragma unroll
        for (int kk = 0; kk < 16; kk++) {
            float4 t0 = *(const float4*)&As[kk][tr * 8];
            float4 t1 = *(const float4*)&As[kk][tr * 8 + 4];
            float4 t2 = *(const float4*)&Bs[kk][tc * 4];
            float a[8] = {t0.x, t0.y, t0.z, t0.w, t1.x, t1.y, t1.z, t1.w};
            float b[4] = {t2.x, t2.y, t2.z, t2.w};
#pragma unroll
            for (int i = 0; i < 8; i++)
#pragma unroll
                for (int j = 0; j < 4; j++) acc[i][j] += a[i] * b[j];
        }
        __syncthreads();
    }

    if (MODE == 0) {
#pragma unroll
        for (int i = 0; i < 8; i++) {
            int m = m0 + tr * 8 + i;
            int bb = m >> 11, s = m & 2047;
#pragma unroll
            for (int j = 0; j < 4; j++) {
                int n = n0 + tc * 4 + j;
                float v = acc[i][j];
                if (n < 1024) {
                    int h = n >> 7, hd = n & 127;
                    g_Q[(((bb * 8 + h) * 2048) + s) * 128 + hd] = v + g_bqEff[n];
                } else if (n < 1280) {
                    int nn = n - 1024;
                    int h = nn >> 7, hd = nn & 127;
                    g_K[(((bb * 2 + h) * 2048) + s) * 128 + hd] = v + g_bkEff[nn];
                } else {
                    int nn = n - 1280;
                    int h = nn >> 7, hd = nn & 127;
                    g_V[(((bb * 2 + h) * 2048) + s) * 128 + hd] = v + bv[nn];
                }
            }
        }
    } else {
#pragma unroll
        for (int i = 0; i < 8; i++) {
            int m = m0 + tr * 8 + i;
            float4 st = make_float4(acc[i][0], acc[i][1], acc[i][2], acc[i][3]);
            *(float4*)&out[m * 1024 + n0 + tc * 4] = st;
        }
    }
}

// ---------------- RoPE (in-place), cos/sin broadcast over heads
template <int WHICH>
__global__ void rope_k(const float* __restrict__ cosb, const float* __restrict__ sinb) {
    const int NH = (WHICH == 0) ? 8 : 2;
    float* buf = (WHICH == 0) ? g_Q : g_K;
    int idx = blockIdx.x * 256 + threadIdx.x;
    int total = 2 * NH * 2048 * 64;
    if (idx >= total) return;
    int j = idx & 63;
    int t = idx >> 6;
    int s = t & 2047; t >>= 11;
    int h = t % NH;
    int b = t / NH;
    float* p = buf + (((b * NH + h) * 2048) + s) * 128;
    const float* cp = cosb + (b * 2048 + s) * 128;
    const float* sp = sinb + (b * 2048 + s) * 128;
    float x1 = p[j], x2 = p[j + 64];
    p[j]      = x1 * cp[j]      - x2 * sp[j];
    p[j + 64] = x2 * cp[j + 64] + x1 * sp[j + 64];
}

// ---------------- causal flash attention, fp32 SIMT
// Q tile 64 rows, KV tile 32 keys, 128 threads: thread (tr=tid/8, tc=tid%8)
// S-frag 4x4 (rows tr*4.., cols tc*4..); O-frag 4 rows x 16 cols (cols tc*4+32g)
__global__ void __launch_bounds__(128) attn_k() {
    extern __shared__ float sm[];
    float* QsT = sm;                    // [128][68]  (d-major, padded)
    float* KsT = sm + 128 * 68;         // [128][36]
    float* Vs  = KsT + 128 * 36;        // [32][128]  (natural)
    float* Ps  = Vs + 32 * 128;         // [64][36]

    int q0 = blockIdx.x * 64;
    int h = blockIdx.y, b = blockIdx.z;
    int kv = h >> 2;  // G = 4
    const float* Qg = g_Q + (((b * 8 + h) * 2048) + q0) * 128;
    const float* Kg = g_K + ((b * 2 + kv) * 2048) * 128;
    const float* Vg = g_V + ((b * 2 + kv) * 2048) * 128;

    int tid = threadIdx.x;
    int tr = tid >> 3, tc = tid & 7;

    // load Q transposed: QsT[d][r]
    for (int r = 0; r < 64; r++) QsT[tid * 68 + r] = Qg[r * 128 + tid];
    __syncthreads();

    float Of[4][16];
#pragma unroll
    for (int i = 0; i < 4; i++)
#pragma unroll
        for (int c = 0; c < 16; c++) Of[i][c] = 0.f;
    float mrow[4] = {-3e38f, -3e38f, -3e38f, -3e38f};
    float lrow[4] = {0.f, 0.f, 0.f, 0.f};

    int nkt = (q0 >> 5) + 2;  // key tiles up to causal limit
    for (int kt = 0; kt < nkt; kt++) {
        int kbase = kt * 32;
        // load K transposed + V natural
        for (int c = 0; c < 32; c++) KsT[tid * 36 + c] = Kg[(kbase + c) * 128 + tid];
#pragma unroll
        for (int l = 0; l < 8; l++) {
            int idx4 = l * 128 + tid;
            ((float4*)Vs)[idx4] = ((const float4*)(Vg + kbase * 128))[idx4];
        }
        __syncthreads();

        // S = Q K^T (4x4 frag)
        float sf[4][4];
#pragma unroll
        for (int i = 0; i < 4; i++)
#pragma unroll
            for (int j = 0; j < 4; j++) sf[i][j] = 0.f;
#pragma unroll 8
        for (int d = 0; d < 128; d++) {
            float4 tq = *(const float4*)&QsT[d * 68 + tr * 4];
            float4 tk = *(const float4*)&KsT[d * 36 + tc * 4];
            float qa[4] = {tq.x, tq.y, tq.z, tq.w};
            float kb[4] = {tk.x, tk.y, tk.z, tk.w};
#pragma unroll
            for (int i = 0; i < 4; i++)
#pragma unroll
                for (int j = 0; j < 4; j++) sf[i][j] += qa[i] * kb[j];
        }

        // online softmax
#pragma unroll
        for (int i = 0; i < 4; i++) {
            int qg = q0 + tr * 4 + i;
            float mx = -3e38f;
#pragma unroll
            for (int j = 0; j < 4; j++) {
                int kc = kbase + tc * 4 + j;
                float v = (kc <= qg) ? sf[i][j] * SCALE_ATT : -1e30f;
                sf[i][j] = v;
                mx = fmaxf(mx, v);
            }
            mx = fmaxf(mx, __shfl_xor_sync(0xffffffffu, mx, 1));
            mx = fmaxf(mx, __shfl_xor_sync(0xffffffffu, mx, 2));
            mx = fmaxf(mx, __shfl_xor_sync(0xffffffffu, mx, 4));
            float newm = fmaxf(mrow[i], mx);
            float corr = __expf(mrow[i] - newm);
            mrow[i] = newm;
            float ls = 0.f;
#pragma unroll
            for (int j = 0; j < 4; j++) {
                float p = __expf(sf[i][j] - newm);
                sf[i][j] = p;
                ls += p;
            }
            ls += __shfl_xor_sync(0xffffffffu, ls, 1);
            ls += __shfl_xor_sync(0xffffffffu, ls, 2);
            ls += __shfl_xor_sync(0xffffffffu, ls, 4);
            lrow[i] = lrow[i] * corr + ls;
#pragma unroll
            for (int c = 0; c < 16; c++) Of[i][c] *= corr;
            *(float4*)&Ps[(tr * 4 + i) * 36 + tc * 4] =
                make_float4(sf[i][0], sf[i][1], sf[i][2], sf[i][3]);
        }
        __syncthreads();

        // O += P @ V
#pragma unroll 4
        for (int k = 0; k < 32; k++) {
            float pr[4];
#pragma unroll
            for (int i = 0; i < 4; i++) pr[i] = Ps[(tr * 4 + i) * 36 + k];
#pragma unroll
            for (int g = 0; g < 4; g++) {
                float4 vv = *(const float4*)&Vs[k * 128 + tc * 4 + g * 32];
                float vx[4] = {vv.x, vv.y, vv.z, vv.w};
#pragma unroll
                for (int i = 0; i < 4; i++)
#pragma unroll
                    for (int u = 0; u < 4; u++) Of[i][g * 4 + u] += pr[i] * vx[u];
            }
        }
        __syncthreads();
    }

    // epilogue: normalize and store to (B,S,H,HD)
#pragma unroll
    for (int i = 0; i < 4; i++) {
        float inv = 1.f / lrow[i];
        int qrow = q0 + tr * 4 + i;
        float* op = g_O + (((b * 2048 + qrow) * 8) + h) * 128;
#pragma unroll
        for (int g = 0; g < 4; g++) {
            float4 st = make_float4(Of[i][g * 4 + 0] * inv, Of[i][g * 4 + 1] * inv,
                                    Of[i][g * 4 + 2] * inv, Of[i][g * 4 + 3] * inv);
            *(float4*)&op[tc * 4 + g * 32] = st;
        }
    }
}

// ---------------- launch ----------------
extern "C" void kernel_launch(void* const* d_in, const int* in_sizes, int n_in,
                              void* d_out, int out_size) {
    const float* hs   = (const float*)d_in[0];
    const float* cosb = (const float*)d_in[1];
    const float* sinb = (const float*)d_in[2];
    // d_in[3] attention_mask: exactly causal -> implemented analytically
    const float* qw   = (const float*)d_in[4];
    const float* kw   = (const float*)d_in[5];
    const float* vw   = (const float*)d_in[6];
    const float* ow   = (const float*)d_in[7];
    const float* qb   = (const float*)d_in[8];
    const float* kb   = (const float*)d_in[9];
    const float* vb   = (const float*)d_in[10];
    const float* qmat = (const float*)d_in[11];
    const float* kmat = (const float*)d_in[12];
    // d_in[13], d_in[14]: tau_kv / tau_group — permutation + inverse cancel exactly
    float* out = (float*)d_out;

    const int ATTN_SMEM = (128 * 68 + 128 * 36 + 32 * 128 + 64 * 36) * 4;  // 78848 B
    cudaFuncSetAttribute(attn_k, cudaFuncAttributeMaxDynamicSharedMemorySize, ATTN_SMEM);

    // 1) fold q_mat / k_mat into projection weights + biases
    fold_w_k<0><<<dim3(1024, 4), 256>>>(qw, qmat);
    fold_w_k<1><<<dim3(256, 4), 256>>>(kw, kmat);
    fold_b_k<0><<<4, 256>>>(qb, qmat);
    fold_b_k<1><<<1, 256>>>(kb, kmat);

    // 2) fused QKV projection (M=4096, N=1536) with scatter epilogue
    sgemm_k<0><<<dim3(24, 32), 256>>>(hs, vw, vb, nullptr);

    // 3) RoPE in-place on Q and K
    rope_k<0><<<8192, 256>>>(cosb, sinb);
    rope_k<1><<<2048, 256>>>(cosb, sinb);

    // 4) causal flash attention (GQA, G=4)
    attn_k<<<dim3(32, 8, 2), 128, ATTN_SMEM>>>();

    // 5) output projection (M=4096, N=1024)
    sgemm_k<1><<<dim3(16, 32), 256>>>(nullptr, ow, nullptr, out);
}

// round 9
// speedup vs baseline: 1.0161x; 1.0100x over previous
#include <cuda_runtime.h>
#include <cuda_bf16.h>

// Problem constants
// B=2, S=2048, D=1024, H=8, HKV=2, HD=128, G=4
#define SCALE_ATT 0.08838834764831845f

// ---------------- device scratch (no allocations allowed) ----------------
__device__ float g_WqEff[1024 * 1024];   // folded q_weight (q_mat absorbed)
__device__ float g_WkEff[256 * 1024];    // folded k_weight (k_mat absorbed)
__device__ float g_bqEff[1024];
__device__ float g_bkEff[256];
__device__ float g_Q[2 * 8 * 2048 * 128];   // (B,H,S,HD)
__device__ float g_K[2 * 2 * 2048 * 128];   // (B,HKV,S,HD)
__device__ float g_V[2 * 2 * 2048 * 128];   // (B,HKV,S,HD)
__device__ float g_O[2 * 2048 * 8 * 128];   // (B,S,H,HD) -> rows for final GEMM

// ---------------- weight folding: Weff[h*128+j, d] = sum_i mat[i,j] * W[h*128+i, d]
template <int WHICH>
__global__ void fold_w_k(const float* __restrict__ W, const float* __restrict__ mat) {
    int o = blockIdx.x;            // output row (h*128 + j)
    int h = o >> 7, j = o & 127;
    int d = blockIdx.y * 256 + threadIdx.x;
    const float* wrow = W + (h * 128) * 1024 + d;
    float acc = 0.f;
#pragma unroll 8
    for (int i = 0; i < 128; i++) acc += mat[i * 128 + j] * wrow[i * 1024];
    if (WHICH == 0) g_WqEff[o * 1024 + d] = acc;
    else            g_WkEff[o * 1024 + d] = acc;
}

template <int WHICH>
__global__ void fold_b_k(const float* __restrict__ bias, const float* __restrict__ mat) {
    const int HOUT = (WHICH == 0) ? 1024 : 256;
    int o = blockIdx.x * blockDim.x + threadIdx.x;
    if (o >= HOUT) return;
    int h = o >> 7, j = o & 127;
    float acc = 0.f;
    for (int i = 0; i < 128; i++) acc += bias[h * 128 + i] * mat[i * 128 + j];
    if (WHICH == 0) g_bqEff[o] = acc;
    else            g_bkEff[o] = acc;
}

// ---------------- SGEMM: C[M,N] = A[M,1024] @ W[N,1024]^T (+bias, scatter epilogue)
// BM=128, BN=64, BK=16, 256 threads, 8x4 microtile.
// MODE 0: A = hidden_states, N=1536 (Q|K|V regions), scatter into g_Q/g_K/g_V (+bias)
// MODE 1: A = g_O, W = o_weight, N=1024, plain store to out
template <int MODE>
__global__ void __launch_bounds__(256) sgemm_k(const float* __restrict__ A_,
                                               const float* __restrict__ Wext,
                                               const float* __restrict__ bv,
                                               float* __restrict__ out) {
    __shared__ float As[16][132];  // [k][m], padded
    __shared__ float Bs[16][68];   // [k][n], padded

    const float* Ap = (MODE == 0) ? A_ : (const float*)g_O;
    int n0 = blockIdx.x * 64;
    int m0 = blockIdx.y * 128;

    const float* Bmat;
    int nb;
    if (MODE == 0) {
        if (n0 < 1024)      { Bmat = g_WqEff; nb = n0; }
        else if (n0 < 1280) { Bmat = g_WkEff; nb = n0 - 1024; }
        else                { Bmat = Wext;    nb = n0 - 1280; }   // v_weight
    } else {
        Bmat = Wext; nb = n0;
    }

    int tid = threadIdx.x;
    int tr = tid >> 4;   // 0..15 -> 8 rows each
    int tc = tid & 15;   // 0..15 -> 4 cols each

    float acc[8][4];
#pragma unroll
    for (int i = 0; i < 8; i++)
#pragma unroll
        for (int j = 0; j < 4; j++) acc[i][j] = 0.f;

    for (int k0 = 0; k0 < 1024; k0 += 16) {
#pragma unroll
        for (int l = 0; l < 8; l++) {
            int flat = l * 256 + tid;
            int mm = flat >> 4, kk = flat & 15;
            As[kk][mm] = Ap[(m0 + mm) * 1024 + k0 + kk];
        }
#pragma unroll
        for (int l = 0; l < 4; l++) {
            int flat = l * 256 + tid;
            int mm = flat >> 4, kk = flat & 15;
            Bs[kk][mm] = Bmat[(nb + mm) * 1024 + k0 + kk];
        }
        __syncthreads();
#pragma unroll
        for (int kk = 0; kk < 16; kk++) {
            float4 t0 = *(const float4*)&As[kk][tr * 8];
            float4 t1 = *(const float4*)&As[kk][tr * 8 + 4];
            float4 t2 = *(const float4*)&Bs[kk][tc * 4];
            float a[8] = {t0.x, t0.y, t0.z, t0.w, t1.x, t1.y, t1.z, t1.w};
            float b[4] = {t2.x, t2.y, t2.z, t2.w};
#pragma unroll
            for (int i = 0; i < 8; i++)
#pragma unroll
                for (int j = 0; j < 4; j++) acc[i][j] += a[i] * b[j];
        }
        __syncthreads();
    }

    if (MODE == 0) {
#pragma unroll
        for (int i = 0; i < 8; i++) {
            int m = m0 + tr * 8 + i;
            int bb = m >> 11, s = m & 2047;
#pragma unroll
            for (int j = 0; j < 4; j++) {
                int n = n0 + tc * 4 + j;
                float v = acc[i][j];
                if (n < 1024) {
                    int h = n >> 7, hd = n & 127;
                    g_Q[(((bb * 8 + h) * 2048) + s) * 128 + hd] = v + g_bqEff[n];
                } else if (n < 1280) {
                    int nn = n - 1024;
                    int h = nn >> 7, hd = nn & 127;
                    g_K[(((bb * 2 + h) * 2048) + s) * 128 + hd] = v + g_bkEff[nn];
                } else {
                    int nn = n - 1280;
                    int h = nn >> 7, hd = nn & 127;
                    g_V[(((bb * 2 + h) * 2048) + s) * 128 + hd] = v + bv[nn];
                }
            }
        }
    } else {
#pragma unroll
        for (int i = 0; i < 8; i++) {
            int m = m0 + tr * 8 + i;
            float4 st = make_float4(acc[i][0], acc[i][1], acc[i][2], acc[i][3]);
            *(float4*)&out[m * 1024 + n0 + tc * 4] = st;
        }
    }
}

// ---------------- RoPE (in-place), cos/sin broadcast over heads
template <int WHICH>
__global__ void rope_k(const float* __restrict__ cosb, const float* __restrict__ sinb) {
    const int NH = (WHICH == 0) ? 8 : 2;
    float* buf = (WHICH == 0) ? g_Q : g_K;
    int idx = blockIdx.x * 256 + threadIdx.x;
    int total = 2 * NH * 2048 * 64;
    if (idx >= total) return;
    int j = idx & 63;
    int t = idx >> 6;
    int s = t & 2047; t >>= 11;
    int h = t % NH;
    int b = t / NH;
    float* p = buf + (((b * NH + h) * 2048) + s) * 128;
    const float* cp = cosb + (b * 2048 + s) * 128;
    const float* sp = sinb + (b * 2048 + s) * 128;
    float x1 = p[j], x2 = p[j + 64];
    p[j]      = x1 * cp[j]      - x2 * sp[j];
    p[j + 64] = x2 * cp[j + 64] + x1 * sp[j + 64];
}

// ---------------- causal flash attention, fp32 SIMT
// Q tile 64 rows, KV tile 32 keys, 128 threads: thread (tr=tid/8, tc=tid%8)
// S-frag 4x4 (rows tr*4.., cols tc*4..); O-frag 4 rows x 16 cols (cols tc*4+32g)
__global__ void __launch_bounds__(128) attn_k() {
    extern __shared__ float sm[];
    float* QsT = sm;                    // [128][68]  (d-major, padded)
    float* KsT = sm + 128 * 68;         // [128][36]
    float* Vs  = KsT + 128 * 36;        // [32][128]  (natural)
    float* Ps  = Vs + 32 * 128;         // [64][36]

    int q0 = blockIdx.x * 64;
    int h = blockIdx.y, b = blockIdx.z;
    int kv = h >> 2;  // G = 4
    const float* Qg = g_Q + (((b * 8 + h) * 2048) + q0) * 128;
    const float* Kg = g_K + ((b * 2 + kv) * 2048) * 128;
    const float* Vg = g_V + ((b * 2 + kv) * 2048) * 128;

    int tid = threadIdx.x;
    int tr = tid >> 3, tc = tid & 7;

    // load Q transposed: QsT[d][r]
    for (int r = 0; r < 64; r++) QsT[tid * 68 + r] = Qg[r * 128 + tid];
    __syncthreads();

    float Of[4][16];
#pragma unroll
    for (int i = 0; i < 4; i++)
#pragma unroll
        for (int c = 0; c < 16; c++) Of[i][c] = 0.f;
    float mrow[4] = {-3e38f, -3e38f, -3e38f, -3e38f};
    float lrow[4] = {0.f, 0.f, 0.f, 0.f};

    int nkt = (q0 >> 5) + 2;  // key tiles up to causal limit
    for (int kt = 0; kt < nkt; kt++) {
        int kbase = kt * 32;
        // load K transposed + V natural
        for (int c = 0; c < 32; c++) KsT[tid * 36 + c] = Kg[(kbase + c) * 128 + tid];
#pragma unroll
        for (int l = 0; l < 8; l++) {
            int idx4 = l * 128 + tid;
            ((float4*)Vs)[idx4] = ((const float4*)(Vg + kbase * 128))[idx4];
        }
        __syncthreads();

        // S = Q K^T (4x4 frag)
        float sf[4][4];
#pragma unroll
        for (int i = 0; i < 4; i++)
#pragma unroll
            for (int j = 0; j < 4; j++) sf[i][j] = 0.f;
#pragma unroll 8
        for (int d = 0; d < 128; d++) {
            float4 tq = *(const float4*)&QsT[d * 68 + tr * 4];
            float4 tk = *(const float4*)&KsT[d * 36 + tc * 4];
            float qa[4] = {tq.x, tq.y, tq.z, tq.w};
            float kb[4] = {tk.x, tk.y, tk.z, tk.w};
#pragma unroll
            for (int i = 0; i < 4; i++)
#pragma unroll
                for (int j = 0; j < 4; j++) sf[i][j] += qa[i] * kb[j];
        }

        // online softmax
#pragma unroll
        for (int i = 0; i < 4; i++) {
            int qg = q0 + tr * 4 + i;
            float mx = -3e38f;
#pragma unroll
            for (int j = 0; j < 4; j++) {
                int kc = kbase + tc * 4 + j;
                float v = (kc <= qg) ? sf[i][j] * SCALE_ATT : -1e30f;
                sf[i][j] = v;
                mx = fmaxf(mx, v);
            }
            mx = fmaxf(mx, __shfl_xor_sync(0xffffffffu, mx, 1));
            mx = fmaxf(mx, __shfl_xor_sync(0xffffffffu, mx, 2));
            mx = fmaxf(mx, __shfl_xor_sync(0xffffffffu, mx, 4));
            float newm = fmaxf(mrow[i], mx);
            float corr = __expf(mrow[i] - newm);
            mrow[i] = newm;
            float ls = 0.f;
#pragma unroll
            for (int j = 0; j < 4; j++) {
                float p = __expf(sf[i][j] - newm);
                sf[i][j] = p;
                ls += p;
            }
            ls += __shfl_xor_sync(0xffffffffu, ls, 1);
            ls += __shfl_xor_sync(0xffffffffu, ls, 2);
            ls += __shfl_xor_sync(0xffffffffu, ls, 4);
            lrow[i] = lrow[i] * corr + ls;
#pragma unroll
            for (int c = 0; c < 16; c++) Of[i][c] *= corr;
            *(float4*)&Ps[(tr * 4 + i) * 36 + tc * 4] =
                make_float4(sf[i][0], sf[i][1], sf[i][2], sf[i][3]);
        }
        __syncthreads();

        // O += P @ V
#pragma unroll 4
        for (int k = 0; k < 32; k++) {
            float pr[4];
#pragma unroll
            for (int i = 0; i < 4; i++) pr[i] = Ps[(tr * 4 + i) * 36 + k];
#pragma unroll
            for (int g = 0; g < 4; g++) {
                float4 vv = *(const float4*)&Vs[k * 128 + tc * 4 + g * 32];
                float vx[4] = {vv.x, vv.y, vv.z, vv.w};
#pragma unroll
                for (int i = 0; i < 4; i++)
#pragma unroll
                    for (int u = 0; u < 4; u++) Of[i][g * 4 + u] += pr[i] * vx[u];
            }
        }
        __syncthreads();
    }

    // epilogue: normalize and store to (B,S,H,HD)
#pragma unroll
    for (int i = 0; i < 4; i++) {
        float inv = 1.f / lrow[i];
        int qrow = q0 + tr * 4 + i;
        float* op = g_O + (((b * 2048 + qrow) * 8) + h) * 128;
#pragma unroll
        for (int g = 0; g < 4; g++) {
            float4 st = make_float4(Of[i][g * 4 + 0] * inv, Of[i][g * 4 + 1] * inv,
                                    Of[i][g * 4 + 2] * inv, Of[i][g * 4 + 3] * inv);
            *(float4*)&op[tc * 4 + g * 32] = st;
        }
    }
}

// ---------------- launch ----------------
extern "C" void kernel_launch(void* const* d_in, const int* in_sizes, int n_in,
                              void* d_out, int out_size) {
    const float* hs   = (const float*)d_in[0];
    const float* cosb = (const float*)d_in[1];
    const float* sinb = (const float*)d_in[2];
    // d_in[3] attention_mask: exactly causal -> implemented analytically
    const float* qw   = (const float*)d_in[4];
    const float* kw   = (const float*)d_in[5];
    const float* vw   = (const float*)d_in[6];
    const float* ow   = (const float*)d_in[7];
    const float* qb   = (const float*)d_in[8];
    const float* kb   = (const float*)d_in[9];
    const float* vb   = (const float*)d_in[10];
    const float* qmat = (const float*)d_in[11];
    const float* kmat = (const float*)d_in[12];
    // d_in[13], d_in[14]: tau_kv / tau_group — permutation + inverse cancel exactly
    float* out = (float*)d_out;

    const int ATTN_SMEM = (128 * 68 + 128 * 36 + 32 * 128 + 64 * 36) * 4;  // 78848 B
    cudaFuncSetAttribute(attn_k, cudaFuncAttributeMaxDynamicSharedMemorySize, ATTN_SMEM);

    // 1) fold q_mat / k_mat into projection weights + biases
    fold_w_k<0><<<dim3(1024, 4), 256>>>(qw, qmat);
    fold_w_k<1><<<dim3(256, 4), 256>>>(kw, kmat);
    fold_b_k<0><<<4, 256>>>(qb, qmat);
    fold_b_k<1><<<1, 256>>>(kb, kmat);

    // 2) fused QKV projection (M=4096, N=1536) with scatter epilogue
    sgemm_k<0><<<dim3(24, 32), 256>>>(hs, vw, vb, nullptr);

    // 3) RoPE in-place on Q and K
    rope_k<0><<<8192, 256>>>(cosb, sinb);
    rope_k<1><<<2048, 256>>>(cosb, sinb);

    // 4) causal flash attention (GQA, G=4)
    attn_k<<<dim3(32, 8, 2), 128, ATTN_SMEM>>>();

    // 5) output projection (M=4096, N=1024)
    sgemm_k<1><<<dim3(16, 32), 256>>>(nullptr, ow, nullptr, out);
}

// round 14
// speedup vs baseline: 1.4404x; 1.4176x over previous
#include <cuda_runtime.h>
#include <cuda_bf16.h>
#include <cstdint>

// B=2, S=2048, D=1024, H=8, HKV=2, HD=128, G=4
#define SCALE_ATT 0.08838834764831845f

// ===================== PTX helpers (sm_80-era, safe for sm_103 target) ==========
__device__ __forceinline__ uint32_t smem_u32(const void* p) {
    uint32_t a;
    asm("{ .reg .u64 t; cvta.to.shared.u64 t, %1; cvt.u32.u64 %0, t; }" : "=r"(a) : "l"(p));
    return a;
}
#define SW128(o) ((o) ^ (((o) >> 3) & 0x70))
#define CP_ASYNC16(dst, src) \
    asm volatile("cp.async.cg.shared.global [%0], [%1], 16;" :: "r"(dst), "l"(src))
#define CP_COMMIT() asm volatile("cp.async.commit_group;" ::: "memory")
#define CP_WAIT1()  asm volatile("cp.async.wait_group 1;" ::: "memory")
#define CP_WAIT0()  asm volatile("cp.async.wait_group 0;" ::: "memory")

__device__ __forceinline__ void ldm_x4(uint32_t* r, uint32_t addr) {
    asm volatile("ldmatrix.sync.aligned.m8n8.x4.shared.b16 {%0,%1,%2,%3}, [%4];"
                 : "=r"(r[0]), "=r"(r[1]), "=r"(r[2]), "=r"(r[3]) : "r"(addr));
}
__device__ __forceinline__ void mma_bf16(float* d, const uint32_t* a, const uint32_t* b) {
    asm volatile(
        "mma.sync.aligned.m16n8k16.row.col.f32.bf16.bf16.f32 "
        "{%0,%1,%2,%3}, {%4,%5,%6,%7}, {%8,%9}, {%0,%1,%2,%3};"
        : "+f"(d[0]), "+f"(d[1]), "+f"(d[2]), "+f"(d[3])
        : "r"(a[0]), "r"(a[1]), "r"(a[2]), "r"(a[3]), "r"(b[0]), "r"(b[1]));
}

// ===================== device scratch =====================
__device__ float g_WqEff[1024 * 1024];
__device__ float g_WkEff[256 * 1024];
__device__ float g_bqEff[1024];
__device__ float g_bkEff[256];
__device__ __align__(16) __nv_bfloat16 g_Ah[4096 * 1024], g_Al[4096 * 1024];
__device__ __align__(16) __nv_bfloat16 g_Wh[1536 * 1024], g_Wl[1536 * 1024];
__device__ __align__(16) __nv_bfloat16 g_OWh[1024 * 1024], g_OWl[1024 * 1024];
__device__ __align__(16) __nv_bfloat16 g_AOh[4096 * 1024], g_AOl[4096 * 1024];
__device__ float g_Q[2 * 8 * 2048 * 128];
__device__ float g_K[2 * 2 * 2048 * 128];
__device__ float g_V[2 * 2 * 2048 * 128];
__device__ float g_O[2 * 2048 * 8 * 128];   // (B,S,H,HD)

// ===================== bf16 split =====================
__device__ __forceinline__ void split_store4(__nv_bfloat16* Hd, __nv_bfloat16* Ld,
                                             int idx, float4 v) {
    __nv_bfloat16 h0 = __float2bfloat16(v.x), h1 = __float2bfloat16(v.y);
    __nv_bfloat16 h2 = __float2bfloat16(v.z), h3 = __float2bfloat16(v.w);
    __nv_bfloat16 l0 = __float2bfloat16(v.x - __bfloat162float(h0));
    __nv_bfloat16 l1 = __float2bfloat16(v.y - __bfloat162float(h1));
    __nv_bfloat16 l2 = __float2bfloat16(v.z - __bfloat162float(h2));
    __nv_bfloat16 l3 = __float2bfloat16(v.w - __bfloat162float(h3));
    *(__nv_bfloat162*)&Hd[idx]     = __halves2bfloat162(h0, h1);
    *(__nv_bfloat162*)&Hd[idx + 2] = __halves2bfloat162(h2, h3);
    *(__nv_bfloat162*)&Ld[idx]     = __halves2bfloat162(l0, l1);
    *(__nv_bfloat162*)&Ld[idx + 2] = __halves2bfloat162(l2, l3);
}
__global__ void split_hidden(const float* __restrict__ hs) {
    int t = blockIdx.x * 256 + threadIdx.x;
    split_store4(g_Ah, g_Al, t * 4, ((const float4*)hs)[t]);
}
__global__ void split_qkvw(const float* __restrict__ vw) {
    int t = blockIdx.x * 256 + threadIdx.x;
    int row = t >> 8, c4 = (t & 255) * 4;
    float4 v;
    if (row < 1024)      v = *(const float4*)&g_WqEff[row * 1024 + c4];
    else if (row < 1280) v = *(const float4*)&g_WkEff[(row - 1024) * 1024 + c4];
    else                 v = *(const float4*)&vw[(row - 1280) * 1024 + c4];
    split_store4(g_Wh, g_Wl, row * 1024 + c4, v);
}
__global__ void split_ow(const float* __restrict__ ow) {
    int t = blockIdx.x * 256 + threadIdx.x;
    split_store4(g_OWh, g_OWl, t * 4, ((const float4*)ow)[t]);
}
__global__ void split_ao() {
    int t = blockIdx.x * 256 + threadIdx.x;
    split_store4(g_AOh, g_AOl, t * 4, ((const float4*)g_O)[t]);
}

// ===================== weight folding (proven) =====================
template <int WHICH>
__global__ void fold_w_k(const float* __restrict__ W, const float* __restrict__ mat) {
    int o = blockIdx.x;
    int h = o >> 7, j = o & 127;
    int d = blockIdx.y * 256 + threadIdx.x;
    const float* wrow = W + (h * 128) * 1024 + d;
    float acc = 0.f;
#pragma unroll 8
    for (int i = 0; i < 128; i++) acc += mat[i * 128 + j] * wrow[i * 1024];
    if (WHICH == 0) g_WqEff[o * 1024 + d] = acc;
    else            g_WkEff[o * 1024 + d] = acc;
}
template <int WHICH>
__global__ void fold_b_k(const float* __restrict__ bias, const float* __restrict__ mat) {
    const int HOUT = (WHICH == 0) ? 1024 : 256;
    int o = blockIdx.x * blockDim.x + threadIdx.x;
    if (o >= HOUT) return;
    int h = o >> 7, j = o & 127;
    float acc = 0.f;
    for (int i = 0; i < 128; i++) acc += bias[h * 128 + i] * mat[i * 128 + j];
    if (WHICH == 0) g_bqEff[o] = acc;
    else            g_bkEff[o] = acc;
}

// ===================== HMMA bf16x3 GEMM =====================
// C[4096, N] = A[4096,1024] @ W[N,1024]^T, fp32 accum.
// BM=128, BN=128, BK=64, 256 thr (8 warps, 4m x 2n, each 32x64).
// 2-stage cp.async pipeline, SW128 smem, ldmatrix fragments.
// MODE 0: QKV (N=1536, 12 n-blocks): +bias, scatter to g_Q/g_K/g_V.
// MODE 1: O-proj (N=1024): plain store.
#define TG_SMEM (1024 + 2 * 65536)

template <int MODE>
__global__ void __launch_bounds__(256) tc_gemm(const float* __restrict__ vb,
                                               float* __restrict__ outp) {
    extern __shared__ char sm[];
    const uint32_t base = smem_u32(sm);
    const int tid = threadIdx.x;
    const int wid = tid >> 5, lane = tid & 31;
    const int bx = blockIdx.x;
    const int m0 = blockIdx.y * 128;
    const int n0 = bx * 128;

    const __nv_bfloat16 *Ah_, *Al_, *Bh_, *Bl_;
    if (MODE == 0) { Ah_ = g_Ah; Al_ = g_Al; Bh_ = g_Wh; Bl_ = g_Wl; }
    else           { Ah_ = g_AOh; Al_ = g_AOl; Bh_ = g_OWh; Bl_ = g_OWl; }

    float* bsm = (float*)sm;  // bias [128]
    if (MODE == 0 && tid < 128) {
        int n = n0 + tid;
        float b;
        if (bx < 8)       b = g_bqEff[n];
        else if (bx < 10) b = g_bkEff[n - 1024];
        else              b = vb[n - 1280];
        bsm[tid] = b;
    }

    const int wm = (wid & 3) * 32;
    const int wn = (wid >> 2) * 64;

    float acc[2][8][4];
#pragma unroll
    for (int mt = 0; mt < 2; mt++)
#pragma unroll
        for (int nt = 0; nt < 8; nt++)
#pragma unroll
            for (int i = 0; i < 4; i++) acc[mt][nt][i] = 0.f;

    // stage loader: Ah@+0, Al@+16384, Bh@+32768, Bl@+49152 (each 128x128B, SW128)
    const int lrow = tid >> 3, lc = tid & 7;  // 4 chunks per array per thread
    const uint32_t lso = SW128(lrow * 128 + lc * 16);

#define ISSUE_LOAD(kt_) do {                                                       \
    const uint32_t toff_ = base + 1024 + ((kt_) & 1) * 65536;                      \
    const int kc_ = (kt_) * 64;                                                    \
    _Pragma("unroll")                                                              \
    for (int i_ = 0; i_ < 4; i_++) {                                               \
        int row_ = lrow + i_ * 32;                                                 \
        uint32_t so_ = SW128(row_ * 128 + lc * 16);                                \
        long giA_ = (long)(m0 + row_) * 1024 + kc_ + lc * 8;                       \
        long giB_ = (long)(n0 + row_) * 1024 + kc_ + lc * 8;                       \
        CP_ASYNC16(toff_ + so_,         Ah_ + giA_);                               \
        CP_ASYNC16(toff_ + 16384 + so_, Al_ + giA_);                               \
        CP_ASYNC16(toff_ + 32768 + so_, Bh_ + giB_);                               \
        CP_ASYNC16(toff_ + 49152 + so_, Bl_ + giB_);                               \
    }                                                                              \
} while (0)

    (void)lso;
    ISSUE_LOAD(0);
    CP_COMMIT();

    for (int kt = 0; kt < 16; kt++) {
        if (kt + 1 < 16) { ISSUE_LOAD(kt + 1); CP_COMMIT(); CP_WAIT1(); }
        else             { CP_WAIT0(); }
        __syncthreads();
        const uint32_t toff = base + 1024 + (kt & 1) * 65536;
#pragma unroll
        for (int ks = 0; ks < 4; ks++) {
            uint32_t ah[2][4], al[2][4], bh[4][4], bl[4][4];
#pragma unroll
            for (int mt = 0; mt < 2; mt++) {
                int row = wm + mt * 16 + (lane & 15);
                int kch = ks * 2 + (lane >> 4);
                uint32_t ad = toff + row * 128 + ((kch ^ (row & 7)) * 16);
                ldm_x4(ah[mt], ad);
                ldm_x4(al[mt], ad + 16384);
            }
#pragma unroll
            for (int p = 0; p < 4; p++) {
                int nrow = wn + p * 16 + ((lane >> 4) * 8 + (lane & 7));
                int kch = ks * 2 + ((lane >> 3) & 1);
                uint32_t bd = toff + 32768 + nrow * 128 + ((kch ^ (nrow & 7)) * 16);
                ldm_x4(bh[p], bd);
                ldm_x4(bl[p], bd + 16384);
            }
#pragma unroll
            for (int mt = 0; mt < 2; mt++)
#pragma unroll
                for (int p = 0; p < 4; p++) {
                    mma_bf16(acc[mt][p * 2],     ah[mt], &bh[p][0]);
                    mma_bf16(acc[mt][p * 2 + 1], ah[mt], &bh[p][2]);
                    mma_bf16(acc[mt][p * 2],     ah[mt], &bl[p][0]);
                    mma_bf16(acc[mt][p * 2 + 1], ah[mt], &bl[p][2]);
                    mma_bf16(acc[mt][p * 2],     al[mt], &bh[p][0]);
                    mma_bf16(acc[mt][p * 2 + 1], al[mt], &bh[p][2]);
                }
        }
        __syncthreads();
    }

    // epilogue: c0,c1 -> (row g, col tig*2); c2,c3 -> (row g+8)
    const int g = lane >> 2, tig = lane & 3;
#pragma unroll
    for (int mt = 0; mt < 2; mt++) {
#pragma unroll
        for (int half = 0; half < 2; half++) {
            int m = m0 + wm + mt * 16 + g + half * 8;
            float* rp;
            if (MODE == 0) {
                int b = m >> 11, s = m & 2047;
                if (bx < 8)       rp = g_Q + (((b * 8 + bx) * 2048) + s) * 128;
                else if (bx < 10) rp = g_K + (((b * 2 + (bx - 8)) * 2048) + s) * 128;
                else              rp = g_V + (((b * 2 + (bx - 10)) * 2048) + s) * 128;
            } else {
                rp = outp + (long)m * 1024 + n0;
            }
#pragma unroll
            for (int nt = 0; nt < 8; nt++) {
                int col = wn + nt * 8 + tig * 2;
                float v0 = acc[mt][nt][half * 2 + 0];
                float v1 = acc[mt][nt][half * 2 + 1];
                if (MODE == 0) { v0 += bsm[col]; v1 += bsm[col + 1]; }
                *(float2*)&rp[col] = make_float2(v0, v1);
            }
        }
    }
}

// ===================== RoPE (proven) =====================
template <int WHICH>
__global__ void rope_k(const float* __restrict__ cosb, const float* __restrict__ sinb) {
    const int NH = (WHICH == 0) ? 8 : 2;
    float* buf = (WHICH == 0) ? g_Q : g_K;
    int idx = blockIdx.x * 256 + threadIdx.x;
    int total = 2 * NH * 2048 * 64;
    if (idx >= total) return;
    int j = idx & 63;
    int t = idx >> 6;
    int s = t & 2047; t >>= 11;
    int h = t % NH;
    int b = t / NH;
    float* p = buf + (((b * NH + h) * 2048) + s) * 128;
    const float* cp = cosb + (b * 2048 + s) * 128;
    const float* sp = sinb + (b * 2048 + s) * 128;
    float x1 = p[j], x2 = p[j + 64];
    p[j]      = x1 * cp[j]      - x2 * sp[j];
    p[j + 64] = x2 * cp[j + 64] + x1 * sp[j + 64];
}

// ===================== causal flash attention (proven, fp32 SIMT) ================
__global__ void __launch_bounds__(128) attn_k() {
    extern __shared__ float smf[];
    float* QsT = smf;                   // [128][68]
    float* KsT = smf + 128 * 68;        // [128][36]
    float* Vs  = KsT + 128 * 36;        // [32][128]
    float* Ps  = Vs + 32 * 128;         // [64][36]

    int q0 = blockIdx.x * 64;
    int h = blockIdx.y, b = blockIdx.z;
    int kv = h >> 2;
    const float* Qg = g_Q + (((b * 8 + h) * 2048) + q0) * 128;
    const float* Kg = g_K + ((b * 2 + kv) * 2048) * 128;
    const float* Vg = g_V + ((b * 2 + kv) * 2048) * 128;

    int tid = threadIdx.x;
    int tr = tid >> 3, tc = tid & 7;

    for (int r = 0; r < 64; r++) QsT[tid * 68 + r] = Qg[r * 128 + tid];
    __syncthreads();

    float Of[4][16];
#pragma unroll
    for (int i = 0; i < 4; i++)
#pragma unroll
        for (int c = 0; c < 16; c++) Of[i][c] = 0.f;
    float mrow[4] = {-3e38f, -3e38f, -3e38f, -3e38f};
    float lrow[4] = {0.f, 0.f, 0.f, 0.f};

    int nkt = (q0 >> 5) + 2;
    for (int kt = 0; kt < nkt; kt++) {
        int kbase = kt * 32;
        for (int c = 0; c < 32; c++) KsT[tid * 36 + c] = Kg[(kbase + c) * 128 + tid];
#pragma unroll
        for (int l = 0; l < 8; l++) {
            int idx4 = l * 128 + tid;
            ((float4*)Vs)[idx4] = ((const float4*)(Vg + kbase * 128))[idx4];
        }
        __syncthreads();

        float sf[4][4];
#pragma unroll
        for (int i = 0; i < 4; i++)
#pragma unroll
            for (int j = 0; j < 4; j++) sf[i][j] = 0.f;
#pragma unroll 8
        for (int d = 0; d < 128; d++) {
            float4 tq = *(const float4*)&QsT[d * 68 + tr * 4];
            float4 tk = *(const float4*)&KsT[d * 36 + tc * 4];
            float qa[4] = {tq.x, tq.y, tq.z, tq.w};
            float kb[4] = {tk.x, tk.y, tk.z, tk.w};
#pragma unroll
            for (int i = 0; i < 4; i++)
#pragma unroll
                for (int j = 0; j < 4; j++) sf[i][j] += qa[i] * kb[j];
        }

#pragma unroll
        for (int i = 0; i < 4; i++) {
            int qg = q0 + tr * 4 + i;
            float mx = -3e38f;
#pragma unroll
            for (int j = 0; j < 4; j++) {
                int kc = kbase + tc * 4 + j;
                float v = (kc <= qg) ? sf[i][j] * SCALE_ATT : -1e30f;
                sf[i][j] = v;
                mx = fmaxf(mx, v);
            }
            mx = fmaxf(mx, __shfl_xor_sync(0xffffffffu, mx, 1));
            mx = fmaxf(mx, __shfl_xor_sync(0xffffffffu, mx, 2));
            mx = fmaxf(mx, __shfl_xor_sync(0xffffffffu, mx, 4));
            float newm = fmaxf(mrow[i], mx);
            float corr = __expf(mrow[i] - newm);
            mrow[i] = newm;
            float ls = 0.f;
#pragma unroll
            for (int j = 0; j < 4; j++) {
                float p = __expf(sf[i][j] - newm);
                sf[i][j] = p;
                ls += p;
            }
            ls += __shfl_xor_sync(0xffffffffu, ls, 1);
            ls += __shfl_xor_sync(0xffffffffu, ls, 2);
            ls += __shfl_xor_sync(0xffffffffu, ls, 4);
            lrow[i] = lrow[i] * corr + ls;
#pragma unroll
            for (int c = 0; c < 16; c++) Of[i][c] *= corr;
            *(float4*)&Ps[(tr * 4 + i) * 36 + tc * 4] =
                make_float4(sf[i][0], sf[i][1], sf[i][2], sf[i][3]);
        }
        __syncthreads();

#pragma unroll 4
        for (int k = 0; k < 32; k++) {
            float pr[4];
#pragma unroll
            for (int i = 0; i < 4; i++) pr[i] = Ps[(tr * 4 + i) * 36 + k];
#pragma unroll
            for (int g = 0; g < 4; g++) {
                float4 vv = *(const float4*)&Vs[k * 128 + tc * 4 + g * 32];
                float vx[4] = {vv.x, vv.y, vv.z, vv.w};
#pragma unroll
                for (int i = 0; i < 4; i++)
#pragma unroll
                    for (int u = 0; u < 4; u++) Of[i][g * 4 + u] += pr[i] * vx[u];
            }
        }
        __syncthreads();
    }

#pragma unroll
    for (int i = 0; i < 4; i++) {
        float inv = 1.f / lrow[i];
        int qrow = q0 + tr * 4 + i;
        float* op = g_O + (((b * 2048 + qrow) * 8) + h) * 128;
#pragma unroll
        for (int g = 0; g < 4; g++) {
            float4 st = make_float4(Of[i][g * 4 + 0] * inv, Of[i][g * 4 + 1] * inv,
                                    Of[i][g * 4 + 2] * inv, Of[i][g * 4 + 3] * inv);
            *(float4*)&op[tc * 4 + g * 32] = st;
        }
    }
}

// ===================== launch =====================
extern "C" void kernel_launch(void* const* d_in, const int* in_sizes, int n_in,
                              void* d_out, int out_size) {
    const float* hs   = (const float*)d_in[0];
    const float* cosb = (const float*)d_in[1];
    const float* sinb = (const float*)d_in[2];
    // d_in[3] attention_mask: exactly causal -> analytic
    const float* qw   = (const float*)d_in[4];
    const float* kw   = (const float*)d_in[5];
    const float* vw   = (const float*)d_in[6];
    const float* ow   = (const float*)d_in[7];
    const float* qb   = (const float*)d_in[8];
    const float* kb   = (const float*)d_in[9];
    const float* vb   = (const float*)d_in[10];
    const float* qmat = (const float*)d_in[11];
    const float* kmat = (const float*)d_in[12];
    // d_in[13], d_in[14]: permutations cancel exactly
    float* out = (float*)d_out;

    const int ATTN_SMEM = (128 * 68 + 128 * 36 + 32 * 128 + 64 * 36) * 4;
    cudaFuncSetAttribute(attn_k, cudaFuncAttributeMaxDynamicSharedMemorySize, ATTN_SMEM);
    cudaFuncSetAttribute(tc_gemm<0>, cudaFuncAttributeMaxDynamicSharedMemorySize, TG_SMEM);
    cudaFuncSetAttribute(tc_gemm<1>, cudaFuncAttributeMaxDynamicSharedMemorySize, TG_SMEM);

    // 1) fold q_mat/k_mat into projections
    fold_w_k<0><<<dim3(1024, 4), 256>>>(qw, qmat);
    fold_w_k<1><<<dim3(256, 4), 256>>>(kw, kmat);
    fold_b_k<0><<<4, 256>>>(qb, qmat);
    fold_b_k<1><<<1, 256>>>(kb, kmat);

    // 2) bf16 splits
    split_hidden<<<4096, 256>>>(hs);
    split_qkvw<<<1536, 256>>>(vw);
    split_ow<<<1024, 256>>>(ow);

    // 3) QKV projection on HMMA tensor cores (bf16x3)
    tc_gemm<0><<<dim3(12, 32), 256, TG_SMEM>>>(vb, nullptr);

    // 4) RoPE
    rope_k<0><<<8192, 256>>>(cosb, sinb);
    rope_k<1><<<2048, 256>>>(cosb, sinb);

    // 5) attention (fp32 SIMT, proven)
    attn_k<<<dim3(32, 8, 2), 128, ATTN_SMEM>>>();

    // 6) O-projection on HMMA tensor cores
    split_ao<<<4096, 256>>>();
    tc_gemm<1><<<dim3(8, 32), 256, TG_SMEM>>>(nullptr, out);
}

// round 15
// speedup vs baseline: 2.8497x; 1.9783x over previous
#include <cuda_runtime.h>
#include <cuda_bf16.h>
#include <cstdint>

// B=2, S=2048, D=1024, H=8, HKV=2, HD=128, G=4
#define SCALE_ATT 0.08838834764831845f
#define SC2 (0.08838834764831845f * 1.4426950408889634f)   // SCALE * log2(e)

// ===================== PTX helpers =====================
__device__ __forceinline__ uint32_t smem_u32(const void* p) {
    uint32_t a;
    asm("{ .reg .u64 t; cvta.to.shared.u64 t, %1; cvt.u32.u64 %0, t; }" : "=r"(a) : "l"(p));
    return a;
}
#define SW128(o) ((o) ^ (((o) >> 3) & 0x70))
#define CP_ASYNC16(dst, src) \
    asm volatile("cp.async.cg.shared.global [%0], [%1], 16;" :: "r"(dst), "l"(src))
#define CP_COMMIT() asm volatile("cp.async.commit_group;" ::: "memory")
#define CP_WAIT1()  asm volatile("cp.async.wait_group 1;" ::: "memory")
#define CP_WAIT0()  asm volatile("cp.async.wait_group 0;" ::: "memory")

__device__ __forceinline__ void ldm_x4(uint32_t* r, uint32_t addr) {
    asm volatile("ldmatrix.sync.aligned.m8n8.x4.shared.b16 {%0,%1,%2,%3}, [%4];"
                 : "=r"(r[0]), "=r"(r[1]), "=r"(r[2]), "=r"(r[3]) : "r"(addr));
}
__device__ __forceinline__ void mma_bf16(float* d, const uint32_t* a, const uint32_t* b) {
    asm volatile(
        "mma.sync.aligned.m16n8k16.row.col.f32.bf16.bf16.f32 "
        "{%0,%1,%2,%3}, {%4,%5,%6,%7}, {%8,%9}, {%0,%1,%2,%3};"
        : "+f"(d[0]), "+f"(d[1]), "+f"(d[2]), "+f"(d[3])
        : "r"(a[0]), "r"(a[1]), "r"(a[2]), "r"(a[3]), "r"(b[0]), "r"(b[1]));
}
__device__ __forceinline__ float ex2f(float x) {
    float r; asm("ex2.approx.f32 %0, %1;" : "=f"(r) : "f"(x)); return r;
}
__device__ __forceinline__ uint32_t packbf(__nv_bfloat16 a, __nv_bfloat16 b) {
    __nv_bfloat162 t = __halves2bfloat162(a, b);
    return *(uint32_t*)&t;
}

// ===================== device scratch =====================
__device__ float g_WqEff[1024 * 1024];
__device__ float g_WkEff[256 * 1024];
__device__ float g_bqEff[1024];
__device__ float g_bkEff[256];
__device__ __align__(16) __nv_bfloat16 g_Ah[4096 * 1024], g_Al[4096 * 1024];
__device__ __align__(16) __nv_bfloat16 g_Wh[1536 * 1024], g_Wl[1536 * 1024];
__device__ __align__(16) __nv_bfloat16 g_OWh[1024 * 1024], g_OWl[1024 * 1024];
__device__ __align__(16) __nv_bfloat16 g_AOh[4096 * 1024], g_AOl[4096 * 1024];
__device__ float g_Q[2 * 8 * 2048 * 128];
__device__ float g_K[2 * 2 * 2048 * 128];
__device__ float g_V[2 * 2 * 2048 * 128];
__device__ float g_O[2 * 2048 * 8 * 128];   // (B,S,H,HD)
// bf16 splits for attention
__device__ __align__(16) __nv_bfloat16 g_Qh[2 * 8 * 2048 * 128], g_Ql[2 * 8 * 2048 * 128];
__device__ __align__(16) __nv_bfloat16 g_Kh[2 * 2 * 2048 * 128], g_Kl[2 * 2 * 2048 * 128];
__device__ __align__(16) __nv_bfloat16 g_VTh[2 * 2 * 128 * 2048], g_VTl[2 * 2 * 128 * 2048];

// ===================== bf16 split =====================
__device__ __forceinline__ void split_store4(__nv_bfloat16* Hd, __nv_bfloat16* Ld,
                                             int idx, float4 v) {
    __nv_bfloat16 h0 = __float2bfloat16(v.x), h1 = __float2bfloat16(v.y);
    __nv_bfloat16 h2 = __float2bfloat16(v.z), h3 = __float2bfloat16(v.w);
    __nv_bfloat16 l0 = __float2bfloat16(v.x - __bfloat162float(h0));
    __nv_bfloat16 l1 = __float2bfloat16(v.y - __bfloat162float(h1));
    __nv_bfloat16 l2 = __float2bfloat16(v.z - __bfloat162float(h2));
    __nv_bfloat16 l3 = __float2bfloat16(v.w - __bfloat162float(h3));
    *(__nv_bfloat162*)&Hd[idx]     = __halves2bfloat162(h0, h1);
    *(__nv_bfloat162*)&Hd[idx + 2] = __halves2bfloat162(h2, h3);
    *(__nv_bfloat162*)&Ld[idx]     = __halves2bfloat162(l0, l1);
    *(__nv_bfloat162*)&Ld[idx + 2] = __halves2bfloat162(l2, l3);
}
__global__ void split_hidden(const float* __restrict__ hs) {
    int t = blockIdx.x * 256 + threadIdx.x;
    split_store4(g_Ah, g_Al, t * 4, ((const float4*)hs)[t]);
}
__global__ void split_qkvw(const float* __restrict__ vw) {
    int t = blockIdx.x * 256 + threadIdx.x;
    int row = t >> 8, c4 = (t & 255) * 4;
    float4 v;
    if (row < 1024)      v = *(const float4*)&g_WqEff[row * 1024 + c4];
    else if (row < 1280) v = *(const float4*)&g_WkEff[(row - 1024) * 1024 + c4];
    else                 v = *(const float4*)&vw[(row - 1280) * 1024 + c4];
    split_store4(g_Wh, g_Wl, row * 1024 + c4, v);
}
__global__ void split_ow(const float* __restrict__ ow) {
    int t = blockIdx.x * 256 + threadIdx.x;
    split_store4(g_OWh, g_OWl, t * 4, ((const float4*)ow)[t]);
}
__global__ void split_ao() {
    int t = blockIdx.x * 256 + threadIdx.x;
    split_store4(g_AOh, g_AOl, t * 4, ((const float4*)g_O)[t]);
}

// ===================== weight folding (proven) =====================
template <int WHICH>
__global__ void fold_w_k(const float* __restrict__ W, const float* __restrict__ mat) {
    int o = blockIdx.x;
    int h = o >> 7, j = o & 127;
    int d = blockIdx.y * 256 + threadIdx.x;
    const float* wrow = W + (h * 128) * 1024 + d;
    float acc = 0.f;
#pragma unroll 8
    for (int i = 0; i < 128; i++) acc += mat[i * 128 + j] * wrow[i * 1024];
    if (WHICH == 0) g_WqEff[o * 1024 + d] = acc;
    else            g_WkEff[o * 1024 + d] = acc;
}
template <int WHICH>
__global__ void fold_b_k(const float* __restrict__ bias, const float* __restrict__ mat) {
    const int HOUT = (WHICH == 0) ? 1024 : 256;
    int o = blockIdx.x * blockDim.x + threadIdx.x;
    if (o >= HOUT) return;
    int h = o >> 7, j = o & 127;
    float acc = 0.f;
    for (int i = 0; i < 128; i++) acc += bias[h * 128 + i] * mat[i * 128 + j];
    if (WHICH == 0) g_bqEff[o] = acc;
    else            g_bkEff[o] = acc;
}

// ===================== HMMA bf16x3 GEMM (proven R14) =====================
#define TG_SMEM (1024 + 2 * 65536)
template <int MODE>
__global__ void __launch_bounds__(256) tc_gemm(const float* __restrict__ vb,
                                               float* __restrict__ outp) {
    extern __shared__ char sm[];
    const uint32_t base = smem_u32(sm);
    const int tid = threadIdx.x;
    const int wid = tid >> 5, lane = tid & 31;
    const int bx = blockIdx.x;
    const int m0 = blockIdx.y * 128;
    const int n0 = bx * 128;

    const __nv_bfloat16 *Ah_, *Al_, *Bh_, *Bl_;
    if (MODE == 0) { Ah_ = g_Ah; Al_ = g_Al; Bh_ = g_Wh; Bl_ = g_Wl; }
    else           { Ah_ = g_AOh; Al_ = g_AOl; Bh_ = g_OWh; Bl_ = g_OWl; }

    float* bsm = (float*)sm;
    if (MODE == 0 && tid < 128) {
        int n = n0 + tid;
        float b;
        if (bx < 8)       b = g_bqEff[n];
        else if (bx < 10) b = g_bkEff[n - 1024];
        else              b = vb[n - 1280];
        bsm[tid] = b;
    }

    const int wm = (wid & 3) * 32;
    const int wn = (wid >> 2) * 64;

    float acc[2][8][4];
#pragma unroll
    for (int mt = 0; mt < 2; mt++)
#pragma unroll
        for (int nt = 0; nt < 8; nt++)
#pragma unroll
            for (int i = 0; i < 4; i++) acc[mt][nt][i] = 0.f;

    const int lrow = tid >> 3, lc = tid & 7;

#define ISSUE_LOAD(kt_) do {                                                       \
    const uint32_t toff_ = base + 1024 + ((kt_) & 1) * 65536;                      \
    const int kc_ = (kt_) * 64;                                                    \
    _Pragma("unroll")                                                              \
    for (int i_ = 0; i_ < 4; i_++) {                                               \
        int row_ = lrow + i_ * 32;                                                 \
        uint32_t so_ = SW128(row_ * 128 + lc * 16);                                \
        long giA_ = (long)(m0 + row_) * 1024 + kc_ + lc * 8;                       \
        long giB_ = (long)(n0 + row_) * 1024 + kc_ + lc * 8;                       \
        CP_ASYNC16(toff_ + so_,         Ah_ + giA_);                               \
        CP_ASYNC16(toff_ + 16384 + so_, Al_ + giA_);                               \
        CP_ASYNC16(toff_ + 32768 + so_, Bh_ + giB_);                               \
        CP_ASYNC16(toff_ + 49152 + so_, Bl_ + giB_);                               \
    }                                                                              \
} while (0)

    ISSUE_LOAD(0);
    CP_COMMIT();

    for (int kt = 0; kt < 16; kt++) {
        if (kt + 1 < 16) { ISSUE_LOAD(kt + 1); CP_COMMIT(); CP_WAIT1(); }
        else             { CP_WAIT0(); }
        __syncthreads();
        const uint32_t toff = base + 1024 + (kt & 1) * 65536;
#pragma unroll
        for (int ks = 0; ks < 4; ks++) {
            uint32_t ah[2][4], al[2][4], bh[4][4], bl[4][4];
#pragma unroll
            for (int mt = 0; mt < 2; mt++) {
                int row = wm + mt * 16 + (lane & 15);
                int kch = ks * 2 + (lane >> 4);
                uint32_t ad = toff + row * 128 + ((kch ^ (row & 7)) * 16);
                ldm_x4(ah[mt], ad);
                ldm_x4(al[mt], ad + 16384);
            }
#pragma unroll
            for (int p = 0; p < 4; p++) {
                int nrow = wn + p * 16 + ((lane >> 4) * 8 + (lane & 7));
                int kch = ks * 2 + ((lane >> 3) & 1);
                uint32_t bd = toff + 32768 + nrow * 128 + ((kch ^ (nrow & 7)) * 16);
                ldm_x4(bh[p], bd);
                ldm_x4(bl[p], bd + 16384);
            }
#pragma unroll
            for (int mt = 0; mt < 2; mt++)
#pragma unroll
                for (int p = 0; p < 4; p++) {
                    mma_bf16(acc[mt][p * 2],     ah[mt], &bh[p][0]);
                    mma_bf16(acc[mt][p * 2 + 1], ah[mt], &bh[p][2]);
                    mma_bf16(acc[mt][p * 2],     ah[mt], &bl[p][0]);
                    mma_bf16(acc[mt][p * 2 + 1], ah[mt], &bl[p][2]);
                    mma_bf16(acc[mt][p * 2],     al[mt], &bh[p][0]);
                    mma_bf16(acc[mt][p * 2 + 1], al[mt], &bh[p][2]);
                }
        }
        __syncthreads();
    }

    const int g = lane >> 2, tig = lane & 3;
#pragma unroll
    for (int mt = 0; mt < 2; mt++) {
#pragma unroll
        for (int half = 0; half < 2; half++) {
            int m = m0 + wm + mt * 16 + g + half * 8;
            float* rp;
            if (MODE == 0) {
                int b = m >> 11, s = m & 2047;
                if (bx < 8)       rp = g_Q + (((b * 8 + bx) * 2048) + s) * 128;
                else if (bx < 10) rp = g_K + (((b * 2 + (bx - 8)) * 2048) + s) * 128;
                else              rp = g_V + (((b * 2 + (bx - 10)) * 2048) + s) * 128;
            } else {
                rp = outp + (long)m * 1024 + n0;
            }
#pragma unroll
            for (int nt = 0; nt < 8; nt++) {
                int col = wn + nt * 8 + tig * 2;
                float v0 = acc[mt][nt][half * 2 + 0];
                float v1 = acc[mt][nt][half * 2 + 1];
                if (MODE == 0) { v0 += bsm[col]; v1 += bsm[col + 1]; }
                *(float2*)&rp[col] = make_float2(v0, v1);
            }
        }
    }
}

// ===================== RoPE + bf16 split (Q/K) =====================
template <int WHICH>
__global__ void rope_split(const float* __restrict__ cosb, const float* __restrict__ sinb) {
    const int NH = (WHICH == 0) ? 8 : 2;
    const float* buf = (WHICH == 0) ? g_Q : g_K;
    __nv_bfloat16* Hd = (WHICH == 0) ? g_Qh : g_Kh;
    __nv_bfloat16* Ld = (WHICH == 0) ? g_Ql : g_Kl;
    int idx = blockIdx.x * 256 + threadIdx.x;
    int total = 2 * NH * 2048 * 64;
    if (idx >= total) return;
    int j = idx & 63;
    int t = idx >> 6;
    int s = t & 2047; t >>= 11;
    int h = t % NH;
    int b = t / NH;
    long off = ((long)(b * NH + h) * 2048 + s) * 128;
    const float* cp = cosb + (b * 2048 + s) * 128;
    const float* sp = sinb + (b * 2048 + s) * 128;
    float x1 = buf[off + j], x2 = buf[off + j + 64];
    float y1 = x1 * cp[j]      - x2 * sp[j];
    float y2 = x2 * cp[j + 64] + x1 * sp[j + 64];
    __nv_bfloat16 h1 = __float2bfloat16(y1);
    __nv_bfloat16 h2 = __float2bfloat16(y2);
    Hd[off + j]      = h1;
    Hd[off + j + 64] = h2;
    Ld[off + j]      = __float2bfloat16(y1 - __bfloat162float(h1));
    Ld[off + j + 64] = __float2bfloat16(y2 - __bfloat162float(h2));
}

// ===================== V transpose + split: [bk][s][d] -> [bk][d][s] =========
__global__ void split_vt() {
    __shared__ float tile[32][33];
    int s0 = blockIdx.x * 32, d0 = blockIdx.y * 32, bk = blockIdx.z;
    int tx = threadIdx.x, ty = threadIdx.y;
    tile[ty][tx] = g_V[(long)bk * 2048 * 128 + (long)(s0 + ty) * 128 + d0 + tx];
    __syncthreads();
    float v = tile[tx][ty];   // = V[s0+tx][d0+ty]
    __nv_bfloat16 h = __float2bfloat16(v);
    long o = (long)bk * 128 * 2048 + (long)(d0 + ty) * 2048 + s0 + tx;
    g_VTh[o] = h;
    g_VTl[o] = __float2bfloat16(v - __bfloat162float(h));
}

// ===================== HMMA flash attention =====================
// CTA: 128 q rows, 8 warps x 16 rows. Key tiles of 64, double-buffered.
// smem: Qh[2 sub x 16K] Ql[..] @0..64K; stages @64K + st*64K:
//   Kh sub0@0 sub1@8K, Kl@16K, VTh@32K, VTl@48K.
#define ATT_SMEM (65536 + 2 * 65536)

__global__ void __launch_bounds__(256, 1) attn_mma() {
    extern __shared__ char sm[];
    const uint32_t base = smem_u32(sm);
    const int tid = threadIdx.x, wid = tid >> 5, lane = tid & 31;
    const int qb = 15 - blockIdx.x;       // big blocks first
    const int q0 = qb * 128;
    const int h = blockIdx.y, b = blockIdx.z;
    const int kv = h >> 2;
    const long qoff  = ((long)(b * 8 + h) * 2048 + q0) * 128;
    const long koff  = ((long)(b * 2 + kv) * 2048) * 128;
    const long vtoff = ((long)(b * 2 + kv) * 128) * 2048;
    const int nkt = qb * 2 + 2;

    // ---- Q stage (once) ----
#pragma unroll
    for (int i = 0; i < 16; i++) {
        int id = i * 256 + tid;
        int a = id >> 11, rem = id & 2047;
        int row = rem >> 4, cc = rem & 15, sub = cc >> 3, c = cc & 7;
        uint32_t so = base + a * 32768 + sub * 16384 + SW128(row * 128 + c * 16);
        const __nv_bfloat16* src = (a ? g_Ql : g_Qh) + qoff + (long)row * 128 + sub * 64 + c * 8;
        CP_ASYNC16(so, src);
    }

#define ISSUE_KV(kt_, st_) do {                                                          \
    int kb_ = (kt_) * 64;                                                                \
    uint32_t sb_ = base + 65536 + (st_) * 65536;                                         \
    _Pragma("unroll")                                                                    \
    for (int i_ = 0; i_ < 16; i_++) {                                                    \
        int id_ = i_ * 256 + tid;                                                        \
        if (id_ < 2048) {                                                                \
            int a_ = id_ >> 10, r_ = id_ & 1023;                                         \
            int row_ = r_ >> 4, cc_ = r_ & 15, sub_ = cc_ >> 3, c_ = cc_ & 7;            \
            uint32_t so_ = sb_ + a_ * 16384 + sub_ * 8192 + SW128(row_ * 128 + c_ * 16); \
            const __nv_bfloat16* sp_ = (a_ ? g_Kl : g_Kh) + koff +                       \
                (long)(kb_ + row_) * 128 + sub_ * 64 + c_ * 8;                           \
            CP_ASYNC16(so_, sp_);                                                        \
        } else {                                                                         \
            int id2_ = id_ - 2048;                                                       \
            int a_ = id2_ >> 10, r_ = id2_ & 1023;                                       \
            int dr_ = r_ >> 3, c_ = r_ & 7;                                              \
            uint32_t so_ = sb_ + 32768 + a_ * 16384 + SW128(dr_ * 128 + c_ * 16);        \
            const __nv_bfloat16* sp_ = (a_ ? g_VTl : g_VTh) + vtoff +                    \
                (long)dr_ * 2048 + kb_ + c_ * 8;                                         \
            CP_ASYNC16(so_, sp_);                                                        \
        }                                                                                \
    }                                                                                    \
} while (0)

    ISSUE_KV(0, 0);
    CP_COMMIT();

    const int wm = wid * 16, g = lane >> 2, tig = lane & 3;
    float of[16][4];
#pragma unroll
    for (int v = 0; v < 16; v++)
#pragma unroll
        for (int i = 0; i < 4; i++) of[v][i] = 0.f;
    float m0 = -1e30f, m1 = -1e30f, l0 = 0.f, l1 = 0.f;

    for (int kt = 0; kt < nkt; kt++) {
        if (kt + 1 < nkt) { ISSUE_KV(kt + 1, (kt + 1) & 1); CP_COMMIT(); CP_WAIT1(); }
        else              { CP_WAIT0(); }
        __syncthreads();
        const uint32_t stK = base + 65536 + (kt & 1) * 65536;
        const int kbase = kt * 64;

        // ---- S = Q K^T (bf16x2 split, 3 terms) ----
        float sacc[8][4];
#pragma unroll
        for (int nt = 0; nt < 8; nt++)
#pragma unroll
            for (int i = 0; i < 4; i++) sacc[nt][i] = 0.f;
#pragma unroll
        for (int ks = 0; ks < 8; ks++) {
            int sub = ks >> 2, kk = ks & 3;
            int arow = wm + (lane & 15);
            int akch = kk * 2 + (lane >> 4);
            uint32_t aa = base + sub * 16384 + arow * 128 + ((akch ^ (arow & 7)) * 16);
            uint32_t ahf[4], alf[4];
            ldm_x4(ahf, aa);
            ldm_x4(alf, aa + 32768);
#pragma unroll
            for (int p = 0; p < 4; p++) {
                int nrow = p * 16 + ((lane >> 4) * 8 + (lane & 7));
                int bkch = kk * 2 + ((lane >> 3) & 1);
                uint32_t ba = stK + sub * 8192 + nrow * 128 + ((bkch ^ (nrow & 7)) * 16);
                uint32_t kh[4], kl[4];
                ldm_x4(kh, ba);
                ldm_x4(kl, ba + 16384);
                mma_bf16(sacc[p * 2],     ahf, &kh[0]);
                mma_bf16(sacc[p * 2 + 1], ahf, &kh[2]);
                mma_bf16(sacc[p * 2],     ahf, &kl[0]);
                mma_bf16(sacc[p * 2 + 1], ahf, &kl[2]);
                mma_bf16(sacc[p * 2],     alf, &kh[0]);
                mma_bf16(sacc[p * 2 + 1], alf, &kh[2]);
            }
        }

        // ---- online softmax (exp2 domain), P -> bf16 h/l A-frags ----
        const int qr0 = q0 + wm + g, qr1 = qr0 + 8;
        float mt0 = -1e30f, mt1 = -1e30f;
#pragma unroll
        for (int nt = 0; nt < 8; nt++) {
            int c0 = kbase + nt * 8 + tig * 2, c1 = c0 + 1;
            float v0 = (c0 <= qr0) ? sacc[nt][0] * SC2 : -1e30f;
            float v1 = (c1 <= qr0) ? sacc[nt][1] * SC2 : -1e30f;
            float v2 = (c0 <= qr1) ? sacc[nt][2] * SC2 : -1e30f;
            float v3 = (c1 <= qr1) ? sacc[nt][3] * SC2 : -1e30f;
            sacc[nt][0] = v0; sacc[nt][1] = v1; sacc[nt][2] = v2; sacc[nt][3] = v3;
            mt0 = fmaxf(mt0, fmaxf(v0, v1));
            mt1 = fmaxf(mt1, fmaxf(v2, v3));
        }
        mt0 = fmaxf(mt0, __shfl_xor_sync(0xffffffffu, mt0, 1));
        mt0 = fmaxf(mt0, __shfl_xor_sync(0xffffffffu, mt0, 2));
        mt1 = fmaxf(mt1, __shfl_xor_sync(0xffffffffu, mt1, 1));
        mt1 = fmaxf(mt1, __shfl_xor_sync(0xffffffffu, mt1, 2));
        float mn0 = fmaxf(m0, mt0), mn1 = fmaxf(m1, mt1);
        float cr0 = ex2f(m0 - mn0), cr1 = ex2f(m1 - mn1);
        m0 = mn0; m1 = mn1;

        uint32_t paH[4][4], paL[4][4];
        float ls0 = 0.f, ls1 = 0.f;
#pragma unroll
        for (int nt = 0; nt < 8; nt++) {
            float p0 = ex2f(sacc[nt][0] - mn0);
            float p1 = ex2f(sacc[nt][1] - mn0);
            float p2 = ex2f(sacc[nt][2] - mn1);
            float p3 = ex2f(sacc[nt][3] - mn1);
            ls0 += p0 + p1; ls1 += p2 + p3;
            __nv_bfloat16 h0 = __float2bfloat16(p0), h1b = __float2bfloat16(p1);
            __nv_bfloat16 h2 = __float2bfloat16(p2), h3 = __float2bfloat16(p3);
            __nv_bfloat16 e0 = __float2bfloat16(p0 - __bfloat162float(h0));
            __nv_bfloat16 e1 = __float2bfloat16(p1 - __bfloat162float(h1b));
            __nv_bfloat16 e2 = __float2bfloat16(p2 - __bfloat162float(h2));
            __nv_bfloat16 e3 = __float2bfloat16(p3 - __bfloat162float(h3));
            int kj = nt >> 1, s2 = (nt & 1) * 2;
            paH[kj][s2 + 0] = packbf(h0, h1b);
            paH[kj][s2 + 1] = packbf(h2, h3);
            paL[kj][s2 + 0] = packbf(e0, e1);
            paL[kj][s2 + 1] = packbf(e2, e3);
        }
        l0 = l0 * cr0 + ls0;
        l1 = l1 * cr1 + ls1;
#pragma unroll
        for (int v = 0; v < 16; v++) {
            of[v][0] *= cr0; of[v][1] *= cr0;
            of[v][2] *= cr1; of[v][3] *= cr1;
        }

        // ---- O += P V (bf16x2 split, 3 terms) ----
#pragma unroll
        for (int kj = 0; kj < 4; kj++) {
#pragma unroll
            for (int vg = 0; vg < 8; vg++) {
                int vrow = vg * 16 + ((lane >> 4) * 8 + (lane & 7));
                int vkch = kj * 2 + ((lane >> 3) & 1);
                uint32_t va = stK + 32768 + vrow * 128 + ((vkch ^ (vrow & 7)) * 16);
                uint32_t vh[4], vl[4];
                ldm_x4(vh, va);
                ldm_x4(vl, va + 16384);
                mma_bf16(of[vg * 2],     paH[kj], &vh[0]);
                mma_bf16(of[vg * 2 + 1], paH[kj], &vh[2]);
                mma_bf16(of[vg * 2],     paH[kj], &vl[0]);
                mma_bf16(of[vg * 2 + 1], paH[kj], &vl[2]);
                mma_bf16(of[vg * 2],     paL[kj], &vh[0]);
                mma_bf16(of[vg * 2 + 1], paL[kj], &vh[2]);
            }
        }
        __syncthreads();
    }

    // ---- epilogue ----
    l0 += __shfl_xor_sync(0xffffffffu, l0, 1);
    l0 += __shfl_xor_sync(0xffffffffu, l0, 2);
    l1 += __shfl_xor_sync(0xffffffffu, l1, 1);
    l1 += __shfl_xor_sync(0xffffffffu, l1, 2);
    float li0 = 1.f / l0, li1 = 1.f / l1;
    int r0 = q0 + wm + g, r1 = r0 + 8;
    float* op0 = g_O + ((long)(b * 2048 + r0) * 8 + h) * 128;
    float* op1 = g_O + ((long)(b * 2048 + r1) * 8 + h) * 128;
#pragma unroll
    for (int v = 0; v < 16; v++) {
        int col = v * 8 + tig * 2;
        *(float2*)&op0[col] = make_float2(of[v][0] * li0, of[v][1] * li0);
        *(float2*)&op1[col] = make_float2(of[v][2] * li1, of[v][3] * li1);
    }
}

// ===================== launch =====================
extern "C" void kernel_launch(void* const* d_in, const int* in_sizes, int n_in,
                              void* d_out, int out_size) {
    const float* hs   = (const float*)d_in[0];
    const float* cosb = (const float*)d_in[1];
    const float* sinb = (const float*)d_in[2];
    // d_in[3] attention_mask: exactly causal -> analytic
    const float* qw   = (const float*)d_in[4];
    const float* kw   = (const float*)d_in[5];
    const float* vw   = (const float*)d_in[6];
    const float* ow   = (const float*)d_in[7];
    const float* qb   = (const float*)d_in[8];
    const float* kb   = (const float*)d_in[9];
    const float* vb   = (const float*)d_in[10];
    const float* qmat = (const float*)d_in[11];
    const float* kmat = (const float*)d_in[12];
    // d_in[13], d_in[14]: permutations cancel exactly
    float* out = (float*)d_out;

    cudaFuncSetAttribute(tc_gemm<0>, cudaFuncAttributeMaxDynamicSharedMemorySize, TG_SMEM);
    cudaFuncSetAttribute(tc_gemm<1>, cudaFuncAttributeMaxDynamicSharedMemorySize, TG_SMEM);
    cudaFuncSetAttribute(attn_mma, cudaFuncAttributeMaxDynamicSharedMemorySize, ATT_SMEM);

    // 1) fold q_mat/k_mat into projections
    fold_w_k<0><<<dim3(1024, 4), 256>>>(qw, qmat);
    fold_w_k<1><<<dim3(256, 4), 256>>>(kw, kmat);
    fold_b_k<0><<<4, 256>>>(qb, qmat);
    fold_b_k<1><<<1, 256>>>(kb, kmat);

    // 2) bf16 splits for QKV GEMM
    split_hidden<<<4096, 256>>>(hs);
    split_qkvw<<<1536, 256>>>(vw);
    split_ow<<<1024, 256>>>(ow);

    // 3) QKV projection (HMMA bf16x3)
    tc_gemm<0><<<dim3(12, 32), 256, TG_SMEM>>>(vb, nullptr);

    // 4) RoPE fused with bf16 split; V transpose+split
    rope_split<0><<<8192, 256>>>(cosb, sinb);
    rope_split<1><<<2048, 256>>>(cosb, sinb);
    split_vt<<<dim3(64, 4, 4), dim3(32, 32)>>>();

    // 5) flash attention (HMMA bf16x2-split)
    attn_mma<<<dim3(16, 8, 2), 256, ATT_SMEM>>>();

    // 6) O-projection (HMMA bf16x3)
    split_ao<<<4096, 256>>>();
    tc_gemm<1><<<dim3(8, 32), 256, TG_SMEM>>>(nullptr, out);
}

// round 17
// speedup vs baseline: 3.2492x; 1.1402x over previous
#include <cuda_runtime.h>
#include <cuda_bf16.h>
#include <cstdint>

// B=2, S=2048, D=1024, H=8, HKV=2, HD=128, G=4
#define SCALE_ATT 0.08838834764831845f
#define SC2 (0.08838834764831845f * 1.4426950408889634f)   // SCALE * log2(e)

// ===================== PTX helpers =====================
__device__ __forceinline__ uint32_t smem_u32(const void* p) {
    uint32_t a;
    asm("{ .reg .u64 t; cvta.to.shared.u64 t, %1; cvt.u32.u64 %0, t; }" : "=r"(a) : "l"(p));
    return a;
}
#define SW128(o) ((o) ^ (((o) >> 3) & 0x70))
#define CP_ASYNC16(dst, src) \
    asm volatile("cp.async.cg.shared.global [%0], [%1], 16;" :: "r"(dst), "l"(src))
#define CP_COMMIT() asm volatile("cp.async.commit_group;" ::: "memory")
#define CP_WAIT1()  asm volatile("cp.async.wait_group 1;" ::: "memory")
#define CP_WAIT0()  asm volatile("cp.async.wait_group 0;" ::: "memory")

__device__ __forceinline__ void ldm_x4(uint32_t* r, uint32_t addr) {
    asm volatile("ldmatrix.sync.aligned.m8n8.x4.shared.b16 {%0,%1,%2,%3}, [%4];"
                 : "=r"(r[0]), "=r"(r[1]), "=r"(r[2]), "=r"(r[3]) : "r"(addr));
}
__device__ __forceinline__ void mma_bf16(float* d, const uint32_t* a, const uint32_t* b) {
    asm volatile(
        "mma.sync.aligned.m16n8k16.row.col.f32.bf16.bf16.f32 "
        "{%0,%1,%2,%3}, {%4,%5,%6,%7}, {%8,%9}, {%0,%1,%2,%3};"
        : "+f"(d[0]), "+f"(d[1]), "+f"(d[2]), "+f"(d[3])
        : "r"(a[0]), "r"(a[1]), "r"(a[2]), "r"(a[3]), "r"(b[0]), "r"(b[1]));
}
__device__ __forceinline__ float ex2f(float x) {
    float r; asm("ex2.approx.f32 %0, %1;" : "=f"(r) : "f"(x)); return r;
}
__device__ __forceinline__ uint32_t packbf(__nv_bfloat16 a, __nv_bfloat16 b) {
    __nv_bfloat162 t = __halves2bfloat162(a, b);
    return *(uint32_t*)&t;
}

// ===================== device scratch =====================
__device__ float g_WqEff[1024 * 1024];
__device__ float g_WkEff[256 * 1024];
__device__ float g_bqEff[1024];
__device__ float g_bkEff[256];
__device__ __align__(16) __nv_bfloat16 g_Ah[4096 * 1024], g_Al[4096 * 1024];
__device__ __align__(16) __nv_bfloat16 g_Wh[1536 * 1024], g_Wl[1536 * 1024];
__device__ __align__(16) __nv_bfloat16 g_OWh[1024 * 1024], g_OWl[1024 * 1024];
__device__ __align__(16) __nv_bfloat16 g_AOh[4096 * 1024], g_AOl[4096 * 1024];
__device__ float g_Q[2 * 8 * 2048 * 128];
__device__ float g_K[2 * 2 * 2048 * 128];
__device__ float g_V[2 * 2 * 2048 * 128];
// bf16 splits for attention
__device__ __align__(16) __nv_bfloat16 g_Qh[2 * 8 * 2048 * 128], g_Ql[2 * 8 * 2048 * 128];
__device__ __align__(16) __nv_bfloat16 g_Kh[2 * 2 * 2048 * 128], g_Kl[2 * 2 * 2048 * 128];
__device__ __align__(16) __nv_bfloat16 g_VTh[2 * 2 * 128 * 2048], g_VTl[2 * 2 * 128 * 2048];

// ===================== bf16 split =====================
__device__ __forceinline__ void split_store4(__nv_bfloat16* Hd, __nv_bfloat16* Ld,
                                             long idx, float4 v) {
    __nv_bfloat16 h0 = __float2bfloat16(v.x), h1 = __float2bfloat16(v.y);
    __nv_bfloat16 h2 = __float2bfloat16(v.z), h3 = __float2bfloat16(v.w);
    __nv_bfloat16 l0 = __float2bfloat16(v.x - __bfloat162float(h0));
    __nv_bfloat16 l1 = __float2bfloat16(v.y - __bfloat162float(h1));
    __nv_bfloat16 l2 = __float2bfloat16(v.z - __bfloat162float(h2));
    __nv_bfloat16 l3 = __float2bfloat16(v.w - __bfloat162float(h3));
    *(__nv_bfloat162*)&Hd[idx]     = __halves2bfloat162(h0, h1);
    *(__nv_bfloat162*)&Hd[idx + 2] = __halves2bfloat162(h2, h3);
    *(__nv_bfloat162*)&Ld[idx]     = __halves2bfloat162(l0, l1);
    *(__nv_bfloat162*)&Ld[idx + 2] = __halves2bfloat162(l2, l3);
}

// ===================== fold (weights + biases, one kernel) =====================
__global__ void __launch_bounds__(256) fold_all(const float* __restrict__ qw,
                                                const float* __restrict__ kw,
                                                const float* __restrict__ qbias,
                                                const float* __restrict__ kbias,
                                                const float* __restrict__ qmat,
                                                const float* __restrict__ kmat) {
    int o = blockIdx.x;                    // 0..1023 -> q, 1024..1279 -> k
    int isK = (o >= 1024) ? 1 : 0;
    const float* W   = isK ? kw : qw;
    const float* mat = isK ? kmat : qmat;
    const float* bin = isK ? kbias : qbias;
    int oo = isK ? o - 1024 : o;
    int h = oo >> 7, j = oo & 127;
    int d = blockIdx.y * 256 + threadIdx.x;
    const float* wrow = W + (h * 128) * 1024 + d;
    float acc = 0.f;
#pragma unroll 8
    for (int i = 0; i < 128; i++) acc += mat[i * 128 + j] * wrow[i * 1024];
    if (isK) g_WkEff[oo * 1024 + d] = acc;
    else     g_WqEff[oo * 1024 + d] = acc;
    if (blockIdx.y == 0 && threadIdx.x < 32) {
        int lane = threadIdx.x;
        float ba = 0.f;
#pragma unroll
        for (int i = lane; i < 128; i += 32) ba += bin[h * 128 + i] * mat[i * 128 + j];
#pragma unroll
        for (int s = 16; s > 0; s >>= 1) ba += __shfl_xor_sync(0xffffffffu, ba, s);
        if (lane == 0) {
            if (isK) g_bkEff[oo] = ba;
            else     g_bqEff[oo] = ba;
        }
    }
}

// ===================== all bf16 splits (one kernel) =====================
// items (float4): hidden 1048576 | qkvw 393216 | ow 262144  -> grid 6656 x 256
__global__ void split_all(const float* __restrict__ hs, const float* __restrict__ vw,
                          const float* __restrict__ ow) {
    long t = (long)blockIdx.x * 256 + threadIdx.x;
    if (t < 1048576) {
        split_store4(g_Ah, g_Al, t * 4, ((const float4*)hs)[t]);
    } else if (t < 1441792) {
        long u = t - 1048576;
        int row = (int)(u >> 8), c4 = (int)(u & 255) * 4;
        float4 v;
        if (row < 1024)      v = *(const float4*)&g_WqEff[row * 1024 + c4];
        else if (row < 1280) v = *(const float4*)&g_WkEff[(row - 1024) * 1024 + c4];
        else                 v = *(const float4*)&vw[(row - 1280) * 1024 + c4];
        split_store4(g_Wh, g_Wl, (long)row * 1024 + c4, v);
    } else {
        long u = t - 1441792;
        split_store4(g_OWh, g_OWl, u * 4, ((const float4*)ow)[u]);
    }
}

// ===================== HMMA bf16x3 GEMM (proven R14/R15) =====================
#define TG_SMEM (1024 + 2 * 65536)
template <int MODE>
__global__ void __launch_bounds__(256) tc_gemm(const float* __restrict__ vb,
                                               float* __restrict__ outp) {
    extern __shared__ char sm[];
    const uint32_t base = smem_u32(sm);
    const int tid = threadIdx.x;
    const int wid = tid >> 5, lane = tid & 31;
    const int bx = blockIdx.x;
    const int m0 = blockIdx.y * 128;
    const int n0 = bx * 128;

    const __nv_bfloat16 *Ah_, *Al_, *Bh_, *Bl_;
    if (MODE == 0) { Ah_ = g_Ah; Al_ = g_Al; Bh_ = g_Wh; Bl_ = g_Wl; }
    else           { Ah_ = g_AOh; Al_ = g_AOl; Bh_ = g_OWh; Bl_ = g_OWl; }

    float* bsm = (float*)sm;
    if (MODE == 0 && tid < 128) {
        int n = n0 + tid;
        float b;
        if (bx < 8)       b = g_bqEff[n];
        else if (bx < 10) b = g_bkEff[n - 1024];
        else              b = vb[n - 1280];
        bsm[tid] = b;
    }

    const int wm = (wid & 3) * 32;
    const int wn = (wid >> 2) * 64;

    float acc[2][8][4];
#pragma unroll
    for (int mt = 0; mt < 2; mt++)
#pragma unroll
        for (int nt = 0; nt < 8; nt++)
#pragma unroll
            for (int i = 0; i < 4; i++) acc[mt][nt][i] = 0.f;

    const int lrow = tid >> 3, lc = tid & 7;

#define ISSUE_LOAD(kt_) do {                                                       \
    const uint32_t toff_ = base + 1024 + ((kt_) & 1) * 65536;                      \
    const int kc_ = (kt_) * 64;                                                    \
    _Pragma("unroll")                                                              \
    for (int i_ = 0; i_ < 4; i_++) {                                               \
        int row_ = lrow + i_ * 32;                                                 \
        uint32_t so_ = SW128(row_ * 128 + lc * 16);                                \
        long giA_ = (long)(m0 + row_) * 1024 + kc_ + lc * 8;                       \
        long giB_ = (long)(n0 + row_) * 1024 + kc_ + lc * 8;                       \
        CP_ASYNC16(toff_ + so_,         Ah_ + giA_);                               \
        CP_ASYNC16(toff_ + 16384 + so_, Al_ + giA_);                               \
        CP_ASYNC16(toff_ + 32768 + so_, Bh_ + giB_);                               \
        CP_ASYNC16(toff_ + 49152 + so_, Bl_ + giB_);                               \
    }                                                                              \
} while (0)

    ISSUE_LOAD(0);
    CP_COMMIT();

    for (int kt = 0; kt < 16; kt++) {
        if (kt + 1 < 16) { ISSUE_LOAD(kt + 1); CP_COMMIT(); CP_WAIT1(); }
        else             { CP_WAIT0(); }
        __syncthreads();
        const uint32_t toff = base + 1024 + (kt & 1) * 65536;
#pragma unroll
        for (int ks = 0; ks < 4; ks++) {
            uint32_t ah[2][4], al[2][4], bh[4][4], bl[4][4];
#pragma unroll
            for (int mt = 0; mt < 2; mt++) {
                int row = wm + mt * 16 + (lane & 15);
                int kch = ks * 2 + (lane >> 4);
                uint32_t ad = toff + row * 128 + ((kch ^ (row & 7)) * 16);
                ldm_x4(ah[mt], ad);
                ldm_x4(al[mt], ad + 16384);
            }
#pragma unroll
            for (int p = 0; p < 4; p++) {
                int nrow = wn + p * 16 + ((lane >> 4) * 8 + (lane & 7));
                int kch = ks * 2 + ((lane >> 3) & 1);
                uint32_t bd = toff + 32768 + nrow * 128 + ((kch ^ (nrow & 7)) * 16);
                ldm_x4(bh[p], bd);
                ldm_x4(bl[p], bd + 16384);
            }
#pragma unroll
            for (int mt = 0; mt < 2; mt++)
#pragma unroll
                for (int p = 0; p < 4; p++) {
                    mma_bf16(acc[mt][p * 2],     ah[mt], &bh[p][0]);
                    mma_bf16(acc[mt][p * 2 + 1], ah[mt], &bh[p][2]);
                    mma_bf16(acc[mt][p * 2],     ah[mt], &bl[p][0]);
                    mma_bf16(acc[mt][p * 2 + 1], ah[mt], &bl[p][2]);
                    mma_bf16(acc[mt][p * 2],     al[mt], &bh[p][0]);
                    mma_bf16(acc[mt][p * 2 + 1], al[mt], &bh[p][2]);
                }
        }
        __syncthreads();
    }

    const int g = lane >> 2, tig = lane & 3;
#pragma unroll
    for (int mt = 0; mt < 2; mt++) {
#pragma unroll
        for (int half = 0; half < 2; half++) {
            int m = m0 + wm + mt * 16 + g + half * 8;
            float* rp;
            if (MODE == 0) {
                int b = m >> 11, s = m & 2047;
                if (bx < 8)       rp = g_Q + (((b * 8 + bx) * 2048) + s) * 128;
                else if (bx < 10) rp = g_K + (((b * 2 + (bx - 8)) * 2048) + s) * 128;
                else              rp = g_V + (((b * 2 + (bx - 10)) * 2048) + s) * 128;
            } else {
                rp = outp + (long)m * 1024 + n0;
            }
#pragma unroll
            for (int nt = 0; nt < 8; nt++) {
                int col = wn + nt * 8 + tig * 2;
                float v0 = acc[mt][nt][half * 2 + 0];
                float v1 = acc[mt][nt][half * 2 + 1];
                if (MODE == 0) { v0 += bsm[col]; v1 += bsm[col + 1]; }
                *(float2*)&rp[col] = make_float2(v0, v1);
            }
        }
    }
}

// ===================== attention prep: rope Q/K + V transpose (one kernel) ======
// grid.x: [0,8192) rope-Q, [8192,10240) rope-K, [10240,11264) V-transpose
__global__ void __launch_bounds__(256) prep_attn(const float* __restrict__ cosb,
                                                 const float* __restrict__ sinb) {
    int bid = blockIdx.x;
    if (bid < 10240) {
        int which = (bid >= 8192) ? 1 : 0;
        int lb = which ? bid - 8192 : bid;
        const int NH = which ? 2 : 8;
        const float* buf = which ? g_K : g_Q;
        __nv_bfloat16* Hd = which ? g_Kh : g_Qh;
        __nv_bfloat16* Ld = which ? g_Kl : g_Ql;
        int idx = lb * 256 + threadIdx.x;
        int j = idx & 63;
        int t = idx >> 6;
        int s = t & 2047; t >>= 11;
        int h = t % NH;
        int b = t / NH;
        long off = ((long)(b * NH + h) * 2048 + s) * 128;
        const float* cp = cosb + (b * 2048 + s) * 128;
        const float* sp = sinb + (b * 2048 + s) * 128;
        float x1 = buf[off + j], x2 = buf[off + j + 64];
        float y1 = x1 * cp[j]      - x2 * sp[j];
        float y2 = x2 * cp[j + 64] + x1 * sp[j + 64];
        __nv_bfloat16 h1 = __float2bfloat16(y1);
        __nv_bfloat16 h2 = __float2bfloat16(y2);
        Hd[off + j]      = h1;
        Hd[off + j + 64] = h2;
        Ld[off + j]      = __float2bfloat16(y1 - __bfloat162float(h1));
        Ld[off + j + 64] = __float2bfloat16(y2 - __bfloat162float(h2));
    } else {
        __shared__ float tile[32][33];
        int vb_ = bid - 10240;               // 0..1023
        int s0 = (vb_ & 63) * 32;
        int d0 = ((vb_ >> 6) & 3) * 32;
        int bk = vb_ >> 8;
        int t = threadIdx.x;
#pragma unroll
        for (int i = 0; i < 4; i++) {
            int sy = (t >> 5) + i * 8, dx = t & 31;
            tile[sy][dx] = g_V[(long)bk * 2048 * 128 + (long)(s0 + sy) * 128 + d0 + dx];
        }
        __syncthreads();
#pragma unroll
        for (int i = 0; i < 4; i++) {
            int dy = (t >> 5) + i * 8, sx = t & 31;
            float v = tile[sx][dy];
            __nv_bfloat16 h = __float2bfloat16(v);
            long o = (long)bk * 128 * 2048 + (long)(d0 + dy) * 2048 + s0 + sx;
            g_VTh[o] = h;
            g_VTl[o] = __float2bfloat16(v - __bfloat162float(h));
        }
    }
}

// ===================== HMMA flash attention (paired q-blocks) =====================
// CTA pair p handles q-blocks {p, 15-p}: uniform 34 key-tiles per CTA.
// grid (8, 8, 2) = 128 CTAs = one balanced wave.
#define ATT_SMEM (65536 + 2 * 65536)

__global__ void __launch_bounds__(256, 1) attn_mma() {
    extern __shared__ char sm[];
    const uint32_t base = smem_u32(sm);
    const int tid = threadIdx.x, wid = tid >> 5, lane = tid & 31;
    const int pair = blockIdx.x;
    const int h = blockIdx.y, b = blockIdx.z;
    const int kv = h >> 2;
    const long koff  = ((long)(b * 2 + kv) * 2048) * 128;
    const long vtoff = ((long)(b * 2 + kv) * 128) * 2048;
    const int wm = wid * 16, g = lane >> 2, tig = lane & 3;

#define ISSUE_KV(kt_, st_) do {                                                          \
    int kb_ = (kt_) * 64;                                                                \
    uint32_t sb_ = base + 65536 + (st_) * 65536;                                         \
    _Pragma("unroll")                                                                    \
    for (int i_ = 0; i_ < 16; i_++) {                                                    \
        int id_ = i_ * 256 + tid;                                                        \
        if (id_ < 2048) {                                                                \
            int a_ = id_ >> 10, r_ = id_ & 1023;                                         \
            int row_ = r_ >> 4, cc_ = r_ & 15, sub_ = cc_ >> 3, c_ = cc_ & 7;            \
            uint32_t so_ = sb_ + a_ * 16384 + sub_ * 8192 + SW128(row_ * 128 + c_ * 16); \
            const __nv_bfloat16* sp_ = (a_ ? g_Kl : g_Kh) + koff +                       \
                (long)(kb_ + row_) * 128 + sub_ * 64 + c_ * 8;                           \
            CP_ASYNC16(so_, sp_);                                                        \
        } else {                                                                         \
            int id2_ = id_ - 2048;                                                       \
            int a_ = id2_ >> 10, r_ = id2_ & 1023;                                       \
            int dr_ = r_ >> 3, c_ = r_ & 7;                                              \
            uint32_t so_ = sb_ + 32768 + a_ * 16384 + SW128(dr_ * 128 + c_ * 16);        \
            const __nv_bfloat16* sp_ = (a_ ? g_VTl : g_VTh) + vtoff +                    \
                (long)dr_ * 2048 + kb_ + c_ * 8;                                         \
            CP_ASYNC16(so_, sp_);                                                        \
        }                                                                                \
    }                                                                                    \
} while (0)

    for (int hf = 0; hf < 2; hf++) {
        const int qb = hf ? (15 - pair) : pair;
        const int q0 = qb * 128;
        const long qoff = ((long)(b * 8 + h) * 2048 + q0) * 128;
        const int nkt = qb * 2 + 2;

        // ---- Q stage ----
#pragma unroll
        for (int i = 0; i < 16; i++) {
            int id = i * 256 + tid;
            int a = id >> 11, rem = id & 2047;
            int row = rem >> 4, cc = rem & 15, sub = cc >> 3, c = cc & 7;
            uint32_t so = base + a * 32768 + sub * 16384 + SW128(row * 128 + c * 16);
            const __nv_bfloat16* src = (a ? g_Ql : g_Qh) + qoff + (long)row * 128 + sub * 64 + c * 8;
            CP_ASYNC16(so, src);
        }
        ISSUE_KV(0, 0);
        CP_COMMIT();

        float of[16][4];
#pragma unroll
        for (int v = 0; v < 16; v++)
#pragma unroll
            for (int i = 0; i < 4; i++) of[v][i] = 0.f;
        float m0 = -1e30f, m1 = -1e30f, l0 = 0.f, l1 = 0.f;

        for (int kt = 0; kt < nkt; kt++) {
            if (kt + 1 < nkt) { ISSUE_KV(kt + 1, (kt + 1) & 1); CP_COMMIT(); CP_WAIT1(); }
            else              { CP_WAIT0(); }
            __syncthreads();
            const uint32_t stK = base + 65536 + (kt & 1) * 65536;
            const int kbase = kt * 64;

            // ---- S = Q K^T (3-term bf16 split) ----
            float sacc[8][4];
#pragma unroll
            for (int nt = 0; nt < 8; nt++)
#pragma unroll
                for (int i = 0; i < 4; i++) sacc[nt][i] = 0.f;
#pragma unroll
            for (int ks = 0; ks < 8; ks++) {
                int sub = ks >> 2, kk = ks & 3;
                int arow = wm + (lane & 15);
                int akch = kk * 2 + (lane >> 4);
                uint32_t aa = base + sub * 16384 + arow * 128 + ((akch ^ (arow & 7)) * 16);
                uint32_t ahf[4], alf[4];
                ldm_x4(ahf, aa);
                ldm_x4(alf, aa + 32768);
#pragma unroll
                for (int p = 0; p < 4; p++) {
                    int nrow = p * 16 + ((lane >> 4) * 8 + (lane & 7));
                    int bkch = kk * 2 + ((lane >> 3) & 1);
                    uint32_t ba = stK + sub * 8192 + nrow * 128 + ((bkch ^ (nrow & 7)) * 16);
                    uint32_t kh[4], kl[4];
                    ldm_x4(kh, ba);
                    ldm_x4(kl, ba + 16384);
                    mma_bf16(sacc[p * 2],     ahf, &kh[0]);
                    mma_bf16(sacc[p * 2 + 1], ahf, &kh[2]);
                    mma_bf16(sacc[p * 2],     ahf, &kl[0]);
                    mma_bf16(sacc[p * 2 + 1], ahf, &kl[2]);
                    mma_bf16(sacc[p * 2],     alf, &kh[0]);
                    mma_bf16(sacc[p * 2 + 1], alf, &kh[2]);
                }
            }

            // ---- online softmax ----
            const int qr0 = q0 + wm + g, qr1 = qr0 + 8;
            float mt0 = -1e30f, mt1 = -1e30f;
#pragma unroll
            for (int nt = 0; nt < 8; nt++) {
                int c0 = kbase + nt * 8 + tig * 2, c1 = c0 + 1;
                float v0 = (c0 <= qr0) ? sacc[nt][0] * SC2 : -1e30f;
                float v1 = (c1 <= qr0) ? sacc[nt][1] * SC2 : -1e30f;
                float v2 = (c0 <= qr1) ? sacc[nt][2] * SC2 : -1e30f;
                float v3 = (c1 <= qr1) ? sacc[nt][3] * SC2 : -1e30f;
                sacc[nt][0] = v0; sacc[nt][1] = v1; sacc[nt][2] = v2; sacc[nt][3] = v3;
                mt0 = fmaxf(mt0, fmaxf(v0, v1));
                mt1 = fmaxf(mt1, fmaxf(v2, v3));
            }
            mt0 = fmaxf(mt0, __shfl_xor_sync(0xffffffffu, mt0, 1));
            mt0 = fmaxf(mt0, __shfl_xor_sync(0xffffffffu, mt0, 2));
            mt1 = fmaxf(mt1, __shfl_xor_sync(0xffffffffu, mt1, 1));
            mt1 = fmaxf(mt1, __shfl_xor_sync(0xffffffffu, mt1, 2));
            float mn0 = fmaxf(m0, mt0), mn1 = fmaxf(m1, mt1);
            float cr0 = ex2f(m0 - mn0), cr1 = ex2f(m1 - mn1);
            m0 = mn0; m1 = mn1;

            uint32_t paH[4][4], paL[4][4];
            float ls0 = 0.f, ls1 = 0.f;
#pragma unroll
            for (int nt = 0; nt < 8; nt++) {
                float p0 = ex2f(sacc[nt][0] - mn0);
                float p1 = ex2f(sacc[nt][1] - mn0);
                float p2 = ex2f(sacc[nt][2] - mn1);
                float p3 = ex2f(sacc[nt][3] - mn1);
                ls0 += p0 + p1; ls1 += p2 + p3;
                __nv_bfloat16 h0 = __float2bfloat16(p0), h1b = __float2bfloat16(p1);
                __nv_bfloat16 h2 = __float2bfloat16(p2), h3 = __float2bfloat16(p3);
                __nv_bfloat16 e0 = __float2bfloat16(p0 - __bfloat162float(h0));
                __nv_bfloat16 e1 = __float2bfloat16(p1 - __bfloat162float(h1b));
                __nv_bfloat16 e2 = __float2bfloat16(p2 - __bfloat162float(h2));
                __nv_bfloat16 e3 = __float2bfloat16(p3 - __bfloat162float(h3));
                int kj = nt >> 1, s2 = (nt & 1) * 2;
                paH[kj][s2 + 0] = packbf(h0, h1b);
                paH[kj][s2 + 1] = packbf(h2, h3);
                paL[kj][s2 + 0] = packbf(e0, e1);
                paL[kj][s2 + 1] = packbf(e2, e3);
            }
            l0 = l0 * cr0 + ls0;
            l1 = l1 * cr1 + ls1;
#pragma unroll
            for (int v = 0; v < 16; v++) {
                of[v][0] *= cr0; of[v][1] *= cr0;
                of[v][2] *= cr1; of[v][3] *= cr1;
            }

            // ---- O += P V (3-term bf16 split) ----
#pragma unroll
            for (int kj = 0; kj < 4; kj++) {
#pragma unroll
                for (int vg = 0; vg < 8; vg++) {
                    int vrow = vg * 16 + ((lane >> 4) * 8 + (lane & 7));
                    int vkch = kj * 2 + ((lane >> 3) & 1);
                    uint32_t va = stK + 32768 + vrow * 128 + ((vkch ^ (vrow & 7)) * 16);
                    uint32_t vh[4], vl[4];
                    ldm_x4(vh, va);
                    ldm_x4(vl, va + 16384);
                    mma_bf16(of[vg * 2],     paH[kj], &vh[0]);
                    mma_bf16(of[vg * 2 + 1], paH[kj], &vh[2]);
                    mma_bf16(of[vg * 2],     paH[kj], &vl[0]);
                    mma_bf16(of[vg * 2 + 1], paH[kj], &vl[2]);
                    mma_bf16(of[vg * 2],     paL[kj], &vh[0]);
                    mma_bf16(of[vg * 2 + 1], paL[kj], &vh[2]);
                }
            }
            __syncthreads();
        }

        // ---- epilogue: normalize + bf16 h/l split directly to g_AOh/g_AOl ----
        l0 += __shfl_xor_sync(0xffffffffu, l0, 1);
        l0 += __shfl_xor_sync(0xffffffffu, l0, 2);
        l1 += __shfl_xor_sync(0xffffffffu, l1, 1);
        l1 += __shfl_xor_sync(0xffffffffu, l1, 2);
        float li0 = 1.f / l0, li1 = 1.f / l1;
        int r0 = q0 + wm + g, r1 = r0 + 8;
        long o0 = ((long)(b * 2048 + r0) * 8 + h) * 128;
        long o1 = ((long)(b * 2048 + r1) * 8 + h) * 128;
#pragma unroll
        for (int v = 0; v < 16; v++) {
            int col = v * 8 + tig * 2;
            float a0 = of[v][0] * li0, a1 = of[v][1] * li0;
            float a2 = of[v][2] * li1, a3 = of[v][3] * li1;
            __nv_bfloat16 h0 = __float2bfloat16(a0), h1b = __float2bfloat16(a1);
            __nv_bfloat16 h2 = __float2bfloat16(a2), h3 = __float2bfloat16(a3);
            *(__nv_bfloat162*)&g_AOh[o0 + col] = __halves2bfloat162(h0, h1b);
            *(__nv_bfloat162*)&g_AOl[o0 + col] = __halves2bfloat162(
                __float2bfloat16(a0 - __bfloat162float(h0)),
                __float2bfloat16(a1 - __bfloat162float(h1b)));
            *(__nv_bfloat162*)&g_AOh[o1 + col] = __halves2bfloat162(h2, h3);
            *(__nv_bfloat162*)&g_AOl[o1 + col] = __halves2bfloat162(
                __float2bfloat16(a2 - __bfloat162float(h2)),
                __float2bfloat16(a3 - __bfloat162float(h3)));
        }
        __syncthreads();
    }
}

// ===================== launch =====================
extern "C" void kernel_launch(void* const* d_in, const int* in_sizes, int n_in,
                              void* d_out, int out_size) {
    const float* hs   = (const float*)d_in[0];
    const float* cosb = (const float*)d_in[1];
    const float* sinb = (const float*)d_in[2];
    // d_in[3] attention_mask: exactly causal -> analytic
    const float* qw   = (const float*)d_in[4];
    const float* kw   = (const float*)d_in[5];
    const float* vw   = (const float*)d_in[6];
    const float* ow   = (const float*)d_in[7];
    const float* qb   = (const float*)d_in[8];
    const float* kb   = (const float*)d_in[9];
    const float* vb   = (const float*)d_in[10];
    const float* qmat = (const float*)d_in[11];
    const float* kmat = (const float*)d_in[12];
    // d_in[13], d_in[14]: permutations cancel exactly
    float* out = (float*)d_out;

    cudaFuncSetAttribute(tc_gemm<0>, cudaFuncAttributeMaxDynamicSharedMemorySize, TG_SMEM);
    cudaFuncSetAttribute(tc_gemm<1>, cudaFuncAttributeMaxDynamicSharedMemorySize, TG_SMEM);
    cudaFuncSetAttribute(attn_mma, cudaFuncAttributeMaxDynamicSharedMemorySize, ATT_SMEM);

    // 1) fold q_mat/k_mat + biases (one kernel)
    fold_all<<<dim3(1280, 4), 256>>>(qw, kw, qb, kb, qmat, kmat);

    // 2) all bf16 splits (one kernel)
    split_all<<<6656, 256>>>(hs, vw, ow);

    // 3) QKV projection (HMMA bf16x3)
    tc_gemm<0><<<dim3(12, 32), 256, TG_SMEM>>>(vb, nullptr);

    // 4) RoPE+split Q/K and V transpose+split (one kernel)
    prep_attn<<<11264, 256>>>(cosb, sinb);

    // 5) flash attention, paired q-blocks, bf16 epilogue
    attn_mma<<<dim3(8, 8, 2), 256, ATT_SMEM>>>();

    // 6) O-projection (HMMA bf16x3)
    tc_gemm<1><<<dim3(8, 32), 256, TG_SMEM>>>(nullptr, out);
}